// round 1
// baseline (speedup 1.0000x reference)
#include <cuda_runtime.h>
#include <cuda_bf16.h>
#include <math.h>

// Problem constants
#define BB 2
#define LL 1024
#define DMODEL 768
#define DINNER 1536
#define DSTATE 16
#define DCONV 4
#define DTRANK 48
#define MTOK (BB*LL)            // 2048 token rows
#define XZW (2*DINNER)          // 3072
#define XDBLW (DTRANK + 2*DSTATE) // 80

// ---------------- scratch (device globals; no allocation allowed) ------------
__device__ float g_xz[MTOK * XZW];            // 25.2 MB
__device__ float g_u0[MTOK * DINNER];         // forward u (post conv+silu)
__device__ float g_u1[MTOK * DINNER];         // reverse u
__device__ float g_xd0[MTOK * XDBLW];
__device__ float g_xd1[MTOK * XDBLW];
__device__ float g_de0[MTOK * DINNER];        // delta forward
__device__ float g_de1[MTOK * DINNER];
__device__ float g_y0[MTOK * DINNER];         // scan out (incl. u*D) fwd
__device__ float g_y1[MTOK * DINNER];         // scan out rev
__device__ float g_yt[MTOK * DINNER];         // gated sum

__device__ __forceinline__ float siluf(float x) {
    return x / (1.f + __expf(-x));
}
__device__ __forceinline__ float softplusf(float x) {
    return (x > 20.f) ? x : log1pf(__expf(x));
}

// ---------------- generic tiled NT GEMM: C[m,n] = sum_k A[m,k]*W[n,k] --------
// EPI = 0: plain store. EPI = 1: softplus(acc + bias[n]).
template<int EPI>
__global__ __launch_bounds__(256)
void gemm_nt(const float* __restrict__ A, const float* __restrict__ W,
             float* __restrict__ C, int M, int N, int K,
             int lda, int ldw, int ldc, const float* __restrict__ bias)
{
    const int BM = 64, BN = 64, BK = 16;
    __shared__ float As[BK][BM + 4];
    __shared__ float Ws[BK][BN + 4];

    int tid = threadIdx.x;         // 256 threads
    int tx = tid & 15;             // 0..15 -> N
    int ty = tid >> 4;             // 0..15 -> M
    int m0 = blockIdx.y * BM;
    int n0 = blockIdx.x * BN;

    float acc[4][4];
#pragma unroll
    for (int i = 0; i < 4; i++)
#pragma unroll
        for (int j = 0; j < 4; j++) acc[i][j] = 0.f;

    for (int k0 = 0; k0 < K; k0 += BK) {
#pragma unroll
        for (int i = 0; i < 4; i++) {
            int idx = tid + i * 256;          // 0..1023
            int mm = idx / BK;                // 0..63
            int kk = idx % BK;                // 0..15
            int gm = m0 + mm, gk = k0 + kk;
            As[kk][mm] = (gm < M && gk < K) ? A[(size_t)gm * lda + gk] : 0.f;
            int gn = n0 + mm;
            Ws[kk][mm] = (gn < N && gk < K) ? W[(size_t)gn * ldw + gk] : 0.f;
        }
        __syncthreads();
#pragma unroll
        for (int kk = 0; kk < BK; kk++) {
            float a[4], w[4];
#pragma unroll
            for (int i = 0; i < 4; i++) a[i] = As[kk][ty * 4 + i];
#pragma unroll
            for (int j = 0; j < 4; j++) w[j] = Ws[kk][tx * 4 + j];
#pragma unroll
            for (int i = 0; i < 4; i++)
#pragma unroll
                for (int j = 0; j < 4; j++)
                    acc[i][j] = fmaf(a[i], w[j], acc[i][j]);
        }
        __syncthreads();
    }

#pragma unroll
    for (int i = 0; i < 4; i++) {
        int gm = m0 + ty * 4 + i;
        if (gm >= M) continue;
#pragma unroll
        for (int j = 0; j < 4; j++) {
            int gn = n0 + tx * 4 + j;
            if (gn >= N) continue;
            float v = acc[i][j];
            if (EPI == 1) v = softplusf(v + bias[gn]);
            C[(size_t)gm * ldc + gn] = v;
        }
    }
}

// ------------- depthwise causal (fwd) + anti-causal (rev) conv + silu --------
__global__ void conv_silu_kernel(const float* __restrict__ xz,
                                 const float* __restrict__ wf, const float* __restrict__ bf,
                                 const float* __restrict__ wr, const float* __restrict__ br,
                                 float* __restrict__ uf, float* __restrict__ ur)
{
    int idx = blockIdx.x * blockDim.x + threadIdx.x;
    if (idx >= MTOK * DINNER) return;
    int d = idx % DINNER;
    int t = (idx / DINNER) % LL;
    int b = idx / (DINNER * LL);

    const float* base = xz + (size_t)b * LL * XZW + d;

    float accf = bf[d];
    float accr = br[d];
#pragma unroll
    for (int k = 0; k < DCONV; k++) {
        int tf = t - (DCONV - 1) + k;   // t-3+k
        int tr = t + (DCONV - 1) - k;   // t+3-k
        float vf = (tf >= 0)  ? base[(size_t)tf * XZW] : 0.f;
        float vr = (tr < LL)  ? base[(size_t)tr * XZW] : 0.f;
        accf = fmaf(wf[d * DCONV + k], vf, accf);
        accr = fmaf(wr[d * DCONV + k], vr, accr);
    }
    uf[idx] = siluf(accf);
    ur[idx] = siluf(accr);
}

// ---------------- selective scan: 1 thread = 1 (b,d) channel, 16 states ------
__global__ __launch_bounds__(128)
void scan_kernel(const float* __restrict__ delta,
                 const float* __restrict__ xdbl,
                 const float* __restrict__ u,
                 const float* __restrict__ A_log,
                 const float* __restrict__ Dp,
                 float* __restrict__ y,
                 int reverse)
{
    const int CH = 64;
    __shared__ float sB[CH][DSTATE];
    __shared__ float sC[CH][DSTATE];

    int d = blockIdx.x * 128 + threadIdx.x;     // 0..1535
    int b = blockIdx.y;
    int tid = threadIdx.x;

    float A[DSTATE];
#pragma unroll
    for (int s = 0; s < DSTATE; s++)
        A[s] = -__expf(A_log[d * DSTATE + s]);
    float A0 = A[0];
    float Dv = Dp[d];

    // fast path valid iff A[s] ~= (s+1)*A[0]  (true for the standard init)
    bool ok = true;
#pragma unroll
    for (int s = 0; s < DSTATE; s++)
        ok = ok && (fabsf(A[s] - (float)(s + 1) * A0) <= 1e-3f * fabsf(A[s]) + 1e-6f);

    float h[DSTATE];
#pragma unroll
    for (int s = 0; s < DSTATE; s++) h[s] = 0.f;

    for (int c = 0; c < LL / CH; c++) {
        // stage B,C rows for this chunk (32 floats per timestep)
        __syncthreads();
#pragma unroll
        for (int k = 0; k < (CH * 32) / 128; k++) {
            int j = tid + k * 128;
            int i = j / 32;            // timestep within chunk
            int w = j % 32;            // 0..15 -> B, 16..31 -> C
            int tt = reverse ? (LL - 1 - (c * CH + i)) : (c * CH + i);
            float v = xdbl[(size_t)(b * LL + tt) * XDBLW + DTRANK + w];
            if (w < DSTATE) sB[i][w] = v; else sC[i][w - DSTATE] = v;
        }
        __syncthreads();

        for (int i = 0; i < CH; i++) {
            int tt = reverse ? (LL - 1 - (c * CH + i)) : (c * CH + i);
            size_t m = (size_t)(b * LL + tt);
            float dl = delta[m * DINNER + d];
            float uu = u[m * DINNER + d];
            float du = dl * uu;
            float acc = 0.f;
            if (ok) {
                float p = __expf(dl * A0);
                float w = p;
#pragma unroll
                for (int s = 0; s < DSTATE; s++) {
                    h[s] = fmaf(w, h[s], du * sB[i][s]);
                    acc = fmaf(h[s], sC[i][s], acc);
                    w *= p;
                }
            } else {
#pragma unroll
                for (int s = 0; s < DSTATE; s++) {
                    float e = __expf(dl * A[s]);
                    h[s] = fmaf(e, h[s], du * sB[i][s]);
                    acc = fmaf(h[s], sC[i][s], acc);
                }
            }
            y[m * DINNER + d] = acc + uu * Dv;
        }
    }
}

// ---------------- gate + sum both directions ---------------------------------
__global__ void combine_kernel(const float* __restrict__ xz,
                               const float* __restrict__ ya,
                               const float* __restrict__ yb,
                               float* __restrict__ yt)
{
    int idx = blockIdx.x * blockDim.x + threadIdx.x;
    if (idx >= MTOK * DINNER) return;
    int d = idx % DINNER;
    int m = idx / DINNER;
    float z = xz[(size_t)m * XZW + DINNER + d];
    yt[idx] = siluf(z) * (ya[idx] + yb[idx]);
}

// ---------------- launch -----------------------------------------------------
extern "C" void kernel_launch(void* const* d_in, const int* in_sizes, int n_in,
                              void* d_out, int out_size)
{
    const float* x       = (const float*)d_in[0];
    const float* in_w    = (const float*)d_in[1];
    const float* out_w   = (const float*)d_in[2];
    const float* conv_wf = (const float*)d_in[3];
    const float* conv_bf = (const float*)d_in[4];
    const float* xproj_f = (const float*)d_in[5];
    const float* dt_wf   = (const float*)d_in[6];
    const float* dt_bf   = (const float*)d_in[7];
    const float* alog_f  = (const float*)d_in[8];
    const float* D_f     = (const float*)d_in[9];
    const float* conv_wr = (const float*)d_in[10];
    const float* conv_br = (const float*)d_in[11];
    const float* xproj_r = (const float*)d_in[12];
    const float* dt_wr   = (const float*)d_in[13];
    const float* dt_br   = (const float*)d_in[14];
    const float* alog_r  = (const float*)d_in[15];
    const float* D_r     = (const float*)d_in[16];

    float *xz, *u0, *u1, *xd0, *xd1, *de0, *de1, *y0, *y1, *yt;
    cudaGetSymbolAddress((void**)&xz,  g_xz);
    cudaGetSymbolAddress((void**)&u0,  g_u0);
    cudaGetSymbolAddress((void**)&u1,  g_u1);
    cudaGetSymbolAddress((void**)&xd0, g_xd0);
    cudaGetSymbolAddress((void**)&xd1, g_xd1);
    cudaGetSymbolAddress((void**)&de0, g_de0);
    cudaGetSymbolAddress((void**)&de1, g_de1);
    cudaGetSymbolAddress((void**)&y0,  g_y0);
    cudaGetSymbolAddress((void**)&y1,  g_y1);
    cudaGetSymbolAddress((void**)&yt,  g_yt);

    // 1) xz = x @ in_proj_w^T   (2048 x 3072, K=768)  -- shared by both dirs
    {
        dim3 grid(XZW / 64, MTOK / 64);
        gemm_nt<0><<<grid, 256>>>(x, in_w, xz, MTOK, XZW, DMODEL,
                                  DMODEL, DMODEL, XZW, nullptr);
    }
    // 2) depthwise conv + silu, both directions
    {
        int n = MTOK * DINNER;
        conv_silu_kernel<<<(n + 255) / 256, 256>>>(xz, conv_wf, conv_bf,
                                                   conv_wr, conv_br, u0, u1);
    }
    // 3) x_dbl = u @ x_proj_w^T  (2048 x 80, K=1536), both dirs
    {
        dim3 grid((XDBLW + 63) / 64, MTOK / 64);
        gemm_nt<0><<<grid, 256>>>(u0, xproj_f, xd0, MTOK, XDBLW, DINNER,
                                  DINNER, DINNER, XDBLW, nullptr);
        gemm_nt<0><<<grid, 256>>>(u1, xproj_r, xd1, MTOK, XDBLW, DINNER,
                                  DINNER, DINNER, XDBLW, nullptr);
    }
    // 4) delta = softplus(dt @ dt_w^T + dt_b)  (2048 x 1536, K=48), both dirs
    {
        dim3 grid(DINNER / 64, MTOK / 64);
        gemm_nt<1><<<grid, 256>>>(xd0, dt_wf, de0, MTOK, DINNER, DTRANK,
                                  XDBLW, DTRANK, DINNER, dt_bf);
        gemm_nt<1><<<grid, 256>>>(xd1, dt_wr, de1, MTOK, DINNER, DTRANK,
                                  XDBLW, DTRANK, DINNER, dt_br);
    }
    // 5) selective scans
    {
        dim3 grid(DINNER / 128, BB);
        scan_kernel<<<grid, 128>>>(de0, xd0, u0, alog_f, D_f, y0, 0);
        scan_kernel<<<grid, 128>>>(de1, xd1, u1, alog_r, D_r, y1, 1);
    }
    // 6) gate + sum
    {
        int n = MTOK * DINNER;
        combine_kernel<<<(n + 255) / 256, 256>>>(xz, y0, y1, yt);
    }
    // 7) out = y_tot @ out_proj_w^T  (2048 x 768, K=1536)
    {
        dim3 grid(DMODEL / 64, MTOK / 64);
        gemm_nt<0><<<grid, 256>>>(yt, out_w, (float*)d_out, MTOK, DMODEL, DINNER,
                                  DINNER, DINNER, DMODEL, nullptr);
    }
}

// round 5
// speedup vs baseline: 2.5280x; 2.5280x over previous
#include <cuda_runtime.h>
#include <cuda_bf16.h>
#include <math.h>
#include <stdint.h>

// Problem constants
#define BB 2
#define LL 1024
#define DMODEL 768
#define DINNER 1536
#define DSTATE 16
#define DCONV 4
#define DTRANK 48
#define MTOK (BB*LL)              // 2048 token rows
#define XZW (2*DINNER)            // 3072
#define XDBLW (DTRANK + 2*DSTATE) // 80

// ---------------- scratch (device globals; no allocation allowed) ------------
__device__ float g_xz[MTOK * XZW];
__device__ float g_u0[MTOK * DINNER];
__device__ float g_u1[MTOK * DINNER];
__device__ float g_xd0[MTOK * XDBLW];
__device__ float g_xd1[MTOK * XDBLW];
__device__ float g_de0[MTOK * DINNER];
__device__ float g_de1[MTOK * DINNER];
__device__ float g_y0[MTOK * DINNER];
__device__ float g_y1[MTOK * DINNER];
__device__ float g_yt[MTOK * DINNER];

__device__ __forceinline__ float siluf(float x) {
    return x / (1.f + __expf(-x));
}
__device__ __forceinline__ float softplusf(float x) {
    return (x > 20.f) ? x : log1pf(__expf(x));
}
__device__ __forceinline__ float tf32r(float x) {
    uint32_t u;
    asm("cvt.rna.tf32.f32 %0, %1;" : "=r"(u) : "f"(x));
    return __uint_as_float(u);
}
__device__ __forceinline__ void mma_tf32(float c[4],
                                         uint32_t a0, uint32_t a1, uint32_t a2, uint32_t a3,
                                         uint32_t b0, uint32_t b1) {
    asm volatile(
        "mma.sync.aligned.m16n8k8.row.col.f32.tf32.tf32.f32 "
        "{%0,%1,%2,%3}, {%4,%5,%6,%7}, {%8,%9}, {%0,%1,%2,%3};"
        : "+f"(c[0]), "+f"(c[1]), "+f"(c[2]), "+f"(c[3])
        : "r"(a0), "r"(a1), "r"(a2), "r"(a3), "r"(b0), "r"(b1));
}

// ---------------- tf32 tensor-core NT GEMM -----------------------------------
// C[m,n] = sum_k A[m,k] * W[n,k].   BM=128, BN=64, BK=16, 256 threads (8 warps,
// warp grid 4(m) x 2(n), warp tile 32x32 = 2x4 m16n8k8 MMAs).
// M must be a multiple of 128; K a multiple of 16; N is bounds-checked.
// blockIdx.z selects between two (A,W,C,bias) problem instances (batching).
// EPI = 0: plain store. EPI = 1: softplus(acc + bias[n]).
template<int EPI>
__global__ __launch_bounds__(256)
void gemm_tf32(const float* __restrict__ A0p, const float* __restrict__ A1p,
               const float* __restrict__ W0p, const float* __restrict__ W1p,
               float* __restrict__ C0p, float* __restrict__ C1p,
               const float* __restrict__ bias0, const float* __restrict__ bias1,
               int M, int N, int K, int lda, int ldw, int ldc)
{
    const float* __restrict__ A = blockIdx.z ? A1p : A0p;
    const float* __restrict__ W = blockIdx.z ? W1p : W0p;
    float* __restrict__ C       = blockIdx.z ? C1p : C0p;
    const float* __restrict__ bias = blockIdx.z ? bias1 : bias0;

    __shared__ float As[16][132];   // [k][m]
    __shared__ float Ws[16][68];    // [k][n]

    const int tid  = threadIdx.x;
    const int warp = tid >> 5, lane = tid & 31;
    const int wm = warp & 3, wn = warp >> 2;     // 4 x 2 warp grid
    const int gID = lane >> 2, tig = lane & 3;

    const int m0 = blockIdx.y * 128;
    const int n0 = blockIdx.x * 64;

    float acc[2][4][4];
#pragma unroll
    for (int mt = 0; mt < 2; mt++)
#pragma unroll
        for (int nt = 0; nt < 4; nt++)
#pragma unroll
            for (int r = 0; r < 4; r++) acc[mt][nt][r] = 0.f;

    for (int k0 = 0; k0 < K; k0 += 16) {
        // stage A tile: 128 x 16, 2 float4 per thread
#pragma unroll
        for (int j = 0; j < 2; j++) {
            int v = tid + j * 256;             // 0..511
            int m = v >> 2, kv = v & 3;
            const float4 f = *(const float4*)(A + (size_t)(m0 + m) * lda + k0 + kv * 4);
            As[kv * 4 + 0][m] = tf32r(f.x);
            As[kv * 4 + 1][m] = tf32r(f.y);
            As[kv * 4 + 2][m] = tf32r(f.z);
            As[kv * 4 + 3][m] = tf32r(f.w);
        }
        // stage W tile: 64 x 16, 1 float4 per thread (zero-fill past N)
        {
            int n = tid >> 2, kv = tid & 3;
            float4 f = make_float4(0.f, 0.f, 0.f, 0.f);
            if (n0 + n < N)
                f = *(const float4*)(W + (size_t)(n0 + n) * ldw + k0 + kv * 4);
            Ws[kv * 4 + 0][n] = tf32r(f.x);
            Ws[kv * 4 + 1][n] = tf32r(f.y);
            Ws[kv * 4 + 2][n] = tf32r(f.z);
            Ws[kv * 4 + 3][n] = tf32r(f.w);
        }
        __syncthreads();

#pragma unroll
        for (int ks = 0; ks < 16; ks += 8) {
            uint32_t af[2][4], bf[4][2];
#pragma unroll
            for (int mt = 0; mt < 2; mt++) {
                int r = wm * 32 + mt * 16 + gID;
                af[mt][0] = __float_as_uint(As[ks + tig    ][r]);
                af[mt][1] = __float_as_uint(As[ks + tig    ][r + 8]);
                af[mt][2] = __float_as_uint(As[ks + tig + 4][r]);
                af[mt][3] = __float_as_uint(As[ks + tig + 4][r + 8]);
            }
#pragma unroll
            for (int nt = 0; nt < 4; nt++) {
                int c = wn * 32 + nt * 8 + gID;
                bf[nt][0] = __float_as_uint(Ws[ks + tig    ][c]);
                bf[nt][1] = __float_as_uint(Ws[ks + tig + 4][c]);
            }
#pragma unroll
            for (int mt = 0; mt < 2; mt++)
#pragma unroll
                for (int nt = 0; nt < 4; nt++)
                    mma_tf32(acc[mt][nt], af[mt][0], af[mt][1], af[mt][2], af[mt][3],
                             bf[nt][0], bf[nt][1]);
        }
        __syncthreads();
    }

    // epilogue
#pragma unroll
    for (int mt = 0; mt < 2; mt++) {
        int r = m0 + wm * 32 + mt * 16 + gID;
#pragma unroll
        for (int nt = 0; nt < 4; nt++) {
            int c = n0 + wn * 32 + nt * 8 + tig * 2;
#pragma unroll
            for (int jj = 0; jj < 2; jj++) {
                int gn = c + jj;
                if (gn >= N) continue;
                float v0 = acc[mt][nt][jj];
                float v1 = acc[mt][nt][2 + jj];
                if (EPI == 1) {
                    float b = bias[gn];
                    v0 = softplusf(v0 + b);
                    v1 = softplusf(v1 + b);
                }
                C[(size_t)r * ldc + gn]       = v0;
                C[(size_t)(r + 8) * ldc + gn] = v1;
            }
        }
    }
}

// ------------- depthwise causal (fwd) + anti-causal (rev) conv + silu --------
__global__ void conv_silu_kernel(const float* __restrict__ xz,
                                 const float* __restrict__ wf, const float* __restrict__ bf,
                                 const float* __restrict__ wr, const float* __restrict__ br,
                                 float* __restrict__ uf, float* __restrict__ ur)
{
    int idx = blockIdx.x * blockDim.x + threadIdx.x;
    if (idx >= MTOK * DINNER) return;
    int d = idx % DINNER;
    int t = (idx / DINNER) % LL;
    int b = idx / (DINNER * LL);

    const float* base = xz + (size_t)b * LL * XZW + d;

    float accf = bf[d];
    float accr = br[d];
#pragma unroll
    for (int k = 0; k < DCONV; k++) {
        int tf = t - (DCONV - 1) + k;
        int tr = t + (DCONV - 1) - k;
        float vf = (tf >= 0) ? base[(size_t)tf * XZW] : 0.f;
        float vr = (tr < LL) ? base[(size_t)tr * XZW] : 0.f;
        accf = fmaf(wf[d * DCONV + k], vf, accf);
        accr = fmaf(wr[d * DCONV + k], vr, accr);
    }
    uf[idx] = siluf(accf);
    ur[idx] = siluf(accr);
}

// ---------------- selective scan: 1 thread = 1 (b,d) channel, 16 states ------
// blockIdx.z selects direction (0 = forward, 1 = reverse scan order).
__global__ __launch_bounds__(128)
void scan_kernel(const float* __restrict__ de0p, const float* __restrict__ de1p,
                 const float* __restrict__ xd0p, const float* __restrict__ xd1p,
                 const float* __restrict__ u0p,  const float* __restrict__ u1p,
                 const float* __restrict__ alf,  const float* __restrict__ alr,
                 const float* __restrict__ Dfp,  const float* __restrict__ Drp,
                 float* __restrict__ y0p, float* __restrict__ y1p)
{
    const int reverse = blockIdx.z;
    const float* __restrict__ delta = reverse ? de1p : de0p;
    const float* __restrict__ xdbl  = reverse ? xd1p : xd0p;
    const float* __restrict__ u     = reverse ? u1p  : u0p;
    const float* __restrict__ A_log = reverse ? alr  : alf;
    const float* __restrict__ Dp    = reverse ? Drp  : Dfp;
    float* __restrict__ y           = reverse ? y1p  : y0p;

    const int CH = 64;
    __shared__ float sB[CH][DSTATE];
    __shared__ float sC[CH][DSTATE];

    int d = blockIdx.x * 128 + threadIdx.x;
    int b = blockIdx.y;
    int tid = threadIdx.x;

    float A[DSTATE];
#pragma unroll
    for (int s = 0; s < DSTATE; s++)
        A[s] = -__expf(A_log[d * DSTATE + s]);
    float A0 = A[0];
    float Dv = Dp[d];

    bool ok = true;
#pragma unroll
    for (int s = 0; s < DSTATE; s++)
        ok = ok && (fabsf(A[s] - (float)(s + 1) * A0) <= 1e-3f * fabsf(A[s]) + 1e-6f);

    float h[DSTATE];
#pragma unroll
    for (int s = 0; s < DSTATE; s++) h[s] = 0.f;

    for (int c = 0; c < LL / CH; c++) {
        __syncthreads();
#pragma unroll
        for (int k = 0; k < (CH * 32) / 128; k++) {
            int j = tid + k * 128;
            int i = j / 32;
            int w = j % 32;
            int tt = reverse ? (LL - 1 - (c * CH + i)) : (c * CH + i);
            float v = xdbl[(size_t)(b * LL + tt) * XDBLW + DTRANK + w];
            if (w < DSTATE) sB[i][w] = v; else sC[i][w - DSTATE] = v;
        }
        __syncthreads();

        // software-pipelined delta/u loads
        int tt0 = reverse ? (LL - 1 - c * CH) : (c * CH);
        size_t m0 = (size_t)(b * LL + tt0);
        float dl = delta[m0 * DINNER + d];
        float uu = u[m0 * DINNER + d];

        for (int i = 0; i < CH; i++) {
            float dln = 0.f, uun = 0.f;
            if (i + 1 < CH) {
                int ttn = reverse ? (LL - 1 - (c * CH + i + 1)) : (c * CH + i + 1);
                size_t mn = (size_t)(b * LL + ttn);
                dln = delta[mn * DINNER + d];
                uun = u[mn * DINNER + d];
            }
            int tt = reverse ? (LL - 1 - (c * CH + i)) : (c * CH + i);
            size_t m = (size_t)(b * LL + tt);
            float du = dl * uu;
            float acc = 0.f;
            if (ok) {
                float p = __expf(dl * A0);
                float w = p;
#pragma unroll
                for (int s = 0; s < DSTATE; s++) {
                    h[s] = fmaf(w, h[s], du * sB[i][s]);
                    acc = fmaf(h[s], sC[i][s], acc);
                    w *= p;
                }
            } else {
#pragma unroll
                for (int s = 0; s < DSTATE; s++) {
                    float e = __expf(dl * A[s]);
                    h[s] = fmaf(e, h[s], du * sB[i][s]);
                    acc = fmaf(h[s], sC[i][s], acc);
                }
            }
            y[m * DINNER + d] = acc + uu * Dv;
            dl = dln; uu = uun;
        }
    }
}

// ---------------- gate + sum both directions ---------------------------------
__global__ void combine_kernel(const float* __restrict__ xz,
                               const float* __restrict__ ya,
                               const float* __restrict__ yb,
                               float* __restrict__ yt)
{
    int idx = blockIdx.x * blockDim.x + threadIdx.x;
    if (idx >= MTOK * DINNER) return;
    int d = idx % DINNER;
    int m = idx / DINNER;
    float z = xz[(size_t)m * XZW + DINNER + d];
    yt[idx] = siluf(z) * (ya[idx] + yb[idx]);
}

// ---------------- launch -----------------------------------------------------
extern "C" void kernel_launch(void* const* d_in, const int* in_sizes, int n_in,
                              void* d_out, int out_size)
{
    const float* x       = (const float*)d_in[0];
    const float* in_w    = (const float*)d_in[1];
    const float* out_w   = (const float*)d_in[2];
    const float* conv_wf = (const float*)d_in[3];
    const float* conv_bf = (const float*)d_in[4];
    const float* xproj_f = (const float*)d_in[5];
    const float* dt_wf   = (const float*)d_in[6];
    const float* dt_bf   = (const float*)d_in[7];
    const float* alog_f  = (const float*)d_in[8];
    const float* D_f     = (const float*)d_in[9];
    const float* conv_wr = (const float*)d_in[10];
    const float* conv_br = (const float*)d_in[11];
    const float* xproj_r = (const float*)d_in[12];
    const float* dt_wr   = (const float*)d_in[13];
    const float* dt_br   = (const float*)d_in[14];
    const float* alog_r  = (const float*)d_in[15];
    const float* D_r     = (const float*)d_in[16];

    float *xz, *u0, *u1, *xd0, *xd1, *de0, *de1, *y0, *y1, *yt;
    cudaGetSymbolAddress((void**)&xz,  g_xz);
    cudaGetSymbolAddress((void**)&u0,  g_u0);
    cudaGetSymbolAddress((void**)&u1,  g_u1);
    cudaGetSymbolAddress((void**)&xd0, g_xd0);
    cudaGetSymbolAddress((void**)&xd1, g_xd1);
    cudaGetSymbolAddress((void**)&de0, g_de0);
    cudaGetSymbolAddress((void**)&de1, g_de1);
    cudaGetSymbolAddress((void**)&y0,  g_y0);
    cudaGetSymbolAddress((void**)&y1,  g_y1);
    cudaGetSymbolAddress((void**)&yt,  g_yt);

    // 1) xz = x @ in_proj_w^T   (2048 x 3072, K=768) -- shared by both dirs
    {
        dim3 grid(XZW / 64, MTOK / 128, 1);
        gemm_tf32<0><<<grid, 256>>>(x, x, in_w, in_w, xz, xz, nullptr, nullptr,
                                    MTOK, XZW, DMODEL, DMODEL, DMODEL, XZW);
    }
    // 2) depthwise conv + silu, both directions
    {
        int n = MTOK * DINNER;
        conv_silu_kernel<<<(n + 255) / 256, 256>>>(xz, conv_wf, conv_bf,
                                                   conv_wr, conv_br, u0, u1);
    }
    // 3) x_dbl = u @ x_proj_w^T  (2048 x 80, K=1536), both dirs batched
    {
        dim3 grid((XDBLW + 63) / 64, MTOK / 128, 2);
        gemm_tf32<0><<<grid, 256>>>(u0, u1, xproj_f, xproj_r, xd0, xd1,
                                    nullptr, nullptr,
                                    MTOK, XDBLW, DINNER, DINNER, DINNER, XDBLW);
    }
    // 4) delta = softplus(dt @ dt_w^T + dt_b)  (2048 x 1536, K=48), batched
    {
        dim3 grid(DINNER / 64, MTOK / 128, 2);
        gemm_tf32<1><<<grid, 256>>>(xd0, xd1, dt_wf, dt_wr, de0, de1,
                                    dt_bf, dt_br,
                                    MTOK, DINNER, DTRANK, XDBLW, DTRANK, DINNER);
    }
    // 5) selective scans, both directions in one launch
    {
        dim3 grid(DINNER / 128, BB, 2);
        scan_kernel<<<grid, 128>>>(de0, de1, xd0, xd1, u0, u1,
                                   alog_f, alog_r, D_f, D_r, y0, y1);
    }
    // 6) gate + sum
    {
        int n = MTOK * DINNER;
        combine_kernel<<<(n + 255) / 256, 256>>>(xz, y0, y1, yt);
    }
    // 7) out = y_tot @ out_proj_w^T  (2048 x 768, K=1536)
    {
        dim3 grid(DMODEL / 64, MTOK / 128, 1);
        gemm_tf32<0><<<grid, 256>>>(yt, yt, out_w, out_w, (float*)d_out, (float*)d_out,
                                    nullptr, nullptr,
                                    MTOK, DMODEL, DINNER, DINNER, DINNER, DMODEL);
    }
}

// round 6
// speedup vs baseline: 2.5298x; 1.0007x over previous
#include <cuda_runtime.h>
#include <cuda_bf16.h>
#include <math.h>
#include <stdint.h>

// Problem constants
#define BB 2
#define LL 1024
#define DMODEL 768
#define DINNER 1536
#define DSTATE 16
#define DCONV 4
#define DTRANK 48
#define MTOK (BB*LL)              // 2048 token rows
#define XZW (2*DINNER)            // 3072
#define XDBLW (DTRANK + 2*DSTATE) // 80

// ---------------- scratch (device globals; no allocation allowed) ------------
__device__ float g_xz[MTOK * XZW];
__device__ float g_u0[MTOK * DINNER];
__device__ float g_u1[MTOK * DINNER];
__device__ float g_xd0[MTOK * XDBLW];
__device__ float g_xd1[MTOK * XDBLW];
__device__ float g_de0[MTOK * DINNER];
__device__ float g_de1[MTOK * DINNER];
__device__ float g_p0[MTOK * DINNER];   // exp(delta*A0) forward
__device__ float g_p1[MTOK * DINNER];   // exp(delta*A0) reverse
__device__ float g_y0[MTOK * DINNER];
__device__ float g_y1[MTOK * DINNER];
__device__ float g_yt[MTOK * DINNER];

__device__ __forceinline__ float siluf(float x) {
    return x / (1.f + __expf(-x));
}
__device__ __forceinline__ float softplusf(float x) {
    return (x > 20.f) ? x : log1pf(__expf(x));
}
__device__ __forceinline__ float tf32r(float x) {
    uint32_t u;
    asm("cvt.rna.tf32.f32 %0, %1;" : "=r"(u) : "f"(x));
    return __uint_as_float(u);
}
__device__ __forceinline__ void mma_tf32(float c[4],
                                         uint32_t a0, uint32_t a1, uint32_t a2, uint32_t a3,
                                         uint32_t b0, uint32_t b1) {
    asm volatile(
        "mma.sync.aligned.m16n8k8.row.col.f32.tf32.tf32.f32 "
        "{%0,%1,%2,%3}, {%4,%5,%6,%7}, {%8,%9}, {%0,%1,%2,%3};"
        : "+f"(c[0]), "+f"(c[1]), "+f"(c[2]), "+f"(c[3])
        : "r"(a0), "r"(a1), "r"(a2), "r"(a3), "r"(b0), "r"(b1));
}

// ---------------- tf32 tensor-core NT GEMM, fragment-layout smem -------------
// C[m,n] = sum_k A[m,k] * W[n,k].  BM=128, BN=128, BK=16, 256 threads
// (8 warps: wm = warp&3 covers 32 rows, wn = warp>>2 covers 64 cols;
//  per warp tile: 2(mt) x 8(nt) m16n8k8 MMAs per k8-step).
// Shared tiles are stored in MMA *fragment order*:
//   A: [kstep][mw(8)][lane(32)][reg(4)]  -> LDS.128 per (mt,kstep)
//   B: [kstep][nw(16)][lane(32)][reg(2)] -> LDS.64  per (nt,kstep)
// Double-buffered (2 stages, 32 KB). M,K multiples of 128/16; N bounds-checked.
// blockIdx.z encodes (dir, kchunk): dir = z/ksplit, kchunk = z%ksplit.
// EPI=0 plain, EPI=1 softplus(acc+bias) + p=exp(de*A0[n]) side output.
// SPLIT=1 -> atomicAdd into C (C must be pre-zeroed).
template<int EPI, int SPLIT>
__global__ __launch_bounds__(256)
void gemm_tc(const float* __restrict__ A0p, const float* __restrict__ A1p,
             const float* __restrict__ W0p, const float* __restrict__ W1p,
             float* __restrict__ C0p, float* __restrict__ C1p,
             const float* __restrict__ b0p, const float* __restrict__ b1p,
             float* __restrict__ P0p, float* __restrict__ P1p,
             const float* __restrict__ al0, const float* __restrict__ al1,
             int M, int N, int Kc,
             int lda, int ldw, int ldc, int ksplit)
{
    const int dir = blockIdx.z / ksplit;
    const int kch = blockIdx.z % ksplit;
    const float* __restrict__ A    = dir ? A1p : A0p;
    const float* __restrict__ W    = dir ? W1p : W0p;
    float* __restrict__ C          = dir ? C1p : C0p;
    const float* __restrict__ bias = dir ? b1p : b0p;
    float* __restrict__ P          = dir ? P1p : P0p;
    const float* __restrict__ alog = dir ? al1 : al0;

    __shared__ float As[2][2048];   // fragment-order A stage
    __shared__ float Bs[2][2048];   // fragment-order B stage
    __shared__ float sA0[128];      // EPI1: -exp(A_log[n][0]) per block column

    const int tid  = threadIdx.x;
    const int warp = tid >> 5, lane = tid & 31;
    const int wm = warp & 3, wn = warp >> 2;
    const int gid = lane >> 2, tg = lane & 3;
    const int m0 = blockIdx.y * 128, n0 = blockIdx.x * 128;
    const int kbeg = kch * Kc;

    if (EPI == 1 && tid < 128) {
        int cc = n0 + tid;
        sA0[tid] = (cc < N) ? -__expf(alog[(size_t)cc * DSTATE]) : 0.f;
    }

    // per-thread staging descriptors (pointers advance by 16 per k-chunk)
    const float* aptr[2]; int asts[2];
#pragma unroll
    for (int j = 0; j < 2; j++) {
        int f = tid + j * 256;            // 0..511
        int ks = f >> 8, mw = (f >> 5) & 7, ln = f & 31;
        int g = ln >> 2, t4 = ln & 3;
        aptr[j] = A + (size_t)(m0 + mw * 16 + g) * lda + kbeg + ks * 8 + t4;
        asts[j] = ((ks * 8 + mw) * 32 + ln) * 4;
    }
    const float* bptr[4]; int bsts[4]; bool bok[4];
#pragma unroll
    for (int j = 0; j < 4; j++) {
        int f = tid + j * 256;            // 0..1023
        int ks = f >> 9, nw = (f >> 5) & 15, ln = f & 31;
        int g = ln >> 2, t4 = ln & 3;
        int n = n0 + nw * 8 + g;
        bok[j] = (n < N);
        bptr[j] = W + (size_t)(bok[j] ? n : 0) * ldw + kbeg + ks * 8 + t4;
        bsts[j] = ((ks * 16 + nw) * 32 + ln) * 2;
    }

    float4 ar[2];
    float2 br[4];
#pragma unroll
    for (int j = 0; j < 2; j++) {
        const float* p = aptr[j];
        ar[j] = make_float4(tf32r(__ldg(p)),            tf32r(__ldg(p + 8 * lda)),
                            tf32r(__ldg(p + 4)),        tf32r(__ldg(p + 8 * lda + 4)));
    }
#pragma unroll
    for (int j = 0; j < 4; j++) {
        const float* p = bptr[j];
        br[j].x = bok[j] ? tf32r(__ldg(p))     : 0.f;
        br[j].y = bok[j] ? tf32r(__ldg(p + 4)) : 0.f;
    }
#pragma unroll
    for (int j = 0; j < 2; j++) *(float4*)&As[0][asts[j]] = ar[j];
#pragma unroll
    for (int j = 0; j < 4; j++) *(float2*)&Bs[0][bsts[j]] = br[j];
    __syncthreads();

    float acc[2][8][4];
#pragma unroll
    for (int mt = 0; mt < 2; mt++)
#pragma unroll
        for (int nt = 0; nt < 8; nt++)
#pragma unroll
            for (int r = 0; r < 4; r++) acc[mt][nt][r] = 0.f;

    const int nk = Kc / 16;
    for (int i = 0; i < nk; i++) {
        int cur = i & 1;
        if (i + 1 < nk) {
#pragma unroll
            for (int j = 0; j < 2; j++) {
                aptr[j] += 16;
                const float* p = aptr[j];
                ar[j] = make_float4(tf32r(__ldg(p)),     tf32r(__ldg(p + 8 * lda)),
                                    tf32r(__ldg(p + 4)), tf32r(__ldg(p + 8 * lda + 4)));
            }
#pragma unroll
            for (int j = 0; j < 4; j++) {
                bptr[j] += 16;
                const float* p = bptr[j];
                br[j].x = bok[j] ? tf32r(__ldg(p))     : 0.f;
                br[j].y = bok[j] ? tf32r(__ldg(p + 4)) : 0.f;
            }
        }
#pragma unroll
        for (int ks = 0; ks < 2; ks++) {
            float4 af[2];
            float2 bf[8];
#pragma unroll
            for (int mt = 0; mt < 2; mt++)
                af[mt] = *(const float4*)&As[cur][((ks * 8 + wm * 2 + mt) * 32 + lane) * 4];
#pragma unroll
            for (int nt = 0; nt < 8; nt++)
                bf[nt] = *(const float2*)&Bs[cur][((ks * 16 + wn * 8 + nt) * 32 + lane) * 2];
#pragma unroll
            for (int mt = 0; mt < 2; mt++)
#pragma unroll
                for (int nt = 0; nt < 8; nt++)
                    mma_tf32(acc[mt][nt],
                             __float_as_uint(af[mt].x), __float_as_uint(af[mt].y),
                             __float_as_uint(af[mt].z), __float_as_uint(af[mt].w),
                             __float_as_uint(bf[nt].x), __float_as_uint(bf[nt].y));
        }
        if (i + 1 < nk) {
            int nxt = (i + 1) & 1;
#pragma unroll
            for (int j = 0; j < 2; j++) *(float4*)&As[nxt][asts[j]] = ar[j];
#pragma unroll
            for (int j = 0; j < 4; j++) *(float2*)&Bs[nxt][bsts[j]] = br[j];
            __syncthreads();
        }
    }

    // epilogue
#pragma unroll
    for (int mt = 0; mt < 2; mt++) {
        int r0 = m0 + wm * 32 + mt * 16 + gid;
#pragma unroll
        for (int nt = 0; nt < 8; nt++) {
            int cc = n0 + wn * 64 + nt * 8 + tg * 2;
#pragma unroll
            for (int jj = 0; jj < 2; jj++) {
                int gn = cc + jj;
                if (gn >= N) continue;
                float v0 = acc[mt][nt][jj];
                float v1 = acc[mt][nt][2 + jj];
                if (EPI == 1) {
                    float bv = bias[gn];
                    float a0 = sA0[gn - n0];
                    float d0 = softplusf(v0 + bv);
                    float d1 = softplusf(v1 + bv);
                    C[(size_t)r0 * ldc + gn]       = d0;
                    C[(size_t)(r0 + 8) * ldc + gn] = d1;
                    P[(size_t)r0 * ldc + gn]       = __expf(d0 * a0);
                    P[(size_t)(r0 + 8) * ldc + gn] = __expf(d1 * a0);
                } else if (SPLIT == 1) {
                    atomicAdd(&C[(size_t)r0 * ldc + gn], v0);
                    atomicAdd(&C[(size_t)(r0 + 8) * ldc + gn], v1);
                } else {
                    C[(size_t)r0 * ldc + gn]       = v0;
                    C[(size_t)(r0 + 8) * ldc + gn] = v1;
                }
            }
        }
    }
}

// ---------------- zero-init ---------------------------------------------------
__global__ void zero_kernel(float* __restrict__ p, int n)
{
    int i = blockIdx.x * blockDim.x + threadIdx.x;
    if (i < n) p[i] = 0.f;
}

// ------------- depthwise causal (fwd) + anti-causal (rev) conv + silu --------
__global__ void conv_silu_kernel(const float* __restrict__ xz,
                                 const float* __restrict__ wf, const float* __restrict__ bf,
                                 const float* __restrict__ wr, const float* __restrict__ br,
                                 float* __restrict__ uf, float* __restrict__ ur)
{
    int idx = blockIdx.x * blockDim.x + threadIdx.x;
    if (idx >= MTOK * DINNER) return;
    int d = idx % DINNER;
    int t = (idx / DINNER) % LL;
    int b = idx / (DINNER * LL);

    const float* base = xz + (size_t)b * LL * XZW + d;

    float accf = bf[d];
    float accr = br[d];
#pragma unroll
    for (int k = 0; k < DCONV; k++) {
        int tf = t - (DCONV - 1) + k;
        int tr = t + (DCONV - 1) - k;
        float vf = (tf >= 0) ? base[(size_t)tf * XZW] : 0.f;
        float vr = (tr < LL) ? base[(size_t)tr * XZW] : 0.f;
        accf = fmaf(wf[d * DCONV + k], vf, accf);
        accr = fmaf(wr[d * DCONV + k], vr, accr);
    }
    uf[idx] = siluf(accf);
    ur[idx] = siluf(accr);
}

// ---------------- selective scan: 4 threads per (b,d) channel ----------------
// 256 threads = 64 channels/block. Each thread owns 4 states.
// p = exp(delta*A0) is precomputed (dt-GEMM epilogue); fast path uses the
// geometric-power identity exp(delta*A_s) = p^(s+1), verified per channel.
__global__ __launch_bounds__(256)
void scan4_kernel(const float* __restrict__ de0p, const float* __restrict__ de1p,
                  const float* __restrict__ gp0,  const float* __restrict__ gp1,
                  const float* __restrict__ xd0p, const float* __restrict__ xd1p,
                  const float* __restrict__ u0p,  const float* __restrict__ u1p,
                  const float* __restrict__ alf,  const float* __restrict__ alr,
                  const float* __restrict__ Dfp,  const float* __restrict__ Drp,
                  float* __restrict__ y0p, float* __restrict__ y1p)
{
    const int reverse = blockIdx.z;
    const float* __restrict__ delta = reverse ? de1p : de0p;
    const float* __restrict__ gp    = reverse ? gp1  : gp0;
    const float* __restrict__ xdbl  = reverse ? xd1p : xd0p;
    const float* __restrict__ u     = reverse ? u1p  : u0p;
    const float* __restrict__ A_log = reverse ? alr  : alf;
    const float* __restrict__ Dp    = reverse ? Drp  : Dfp;
    float* __restrict__ y           = reverse ? y1p  : y0p;

    const int CH = 64;
    __shared__ float sBC[CH][32];    // B[0..15], C[16..31]
    __shared__ float sY[CH][64];

    const int tid = threadIdx.x;
    const int ch = tid >> 2, tq = tid & 3;
    const int lane = tid & 31;
    const int d0 = blockIdx.x * 64;
    const int d = d0 + ch;
    const int b = blockIdx.y;

    float A[4];
#pragma unroll
    for (int j = 0; j < 4; j++)
        A[j] = -__expf(A_log[(size_t)d * DSTATE + tq * 4 + j]);
    float A0 = -__expf(A_log[(size_t)d * DSTATE]);
    bool okl = true;
#pragma unroll
    for (int j = 0; j < 4; j++) {
        float t = (float)(tq * 4 + j + 1) * A0;
        okl = okl && (fabsf(A[j] - t) <= 1e-3f * fabsf(A[j]) + 1e-6f);
    }
    unsigned bal = __ballot_sync(0xffffffffu, okl);
    int q = lane & 28;
    bool ok = ((bal >> q) & 0xFu) == 0xFu;
    float Dv = Dp[d];

    float h[4] = {0.f, 0.f, 0.f, 0.f};

    for (int c = 0; c < LL / CH; c++) {
        __syncthreads();
#pragma unroll
        for (int k = 0; k < (CH * 32) / 256; k++) {
            int j = tid + k * 256;
            int i = j >> 5, w = j & 31;
            int tt = reverse ? (LL - 1 - (c * CH + i)) : (c * CH + i);
            sBC[i][w] = xdbl[(size_t)(b * LL + tt) * XDBLW + DTRANK + w];
        }
        __syncthreads();

        int tt0 = reverse ? (LL - 1 - c * CH) : (c * CH);
        size_t m0 = (size_t)(b * LL + tt0) * DINNER + d;
        float dl = delta[m0];
        float uu = u[m0];
        float pp = gp[m0];

        for (int i = 0; i < CH; i++) {
            float dln = 0.f, uun = 0.f, ppn = 0.f;
            if (i + 1 < CH) {
                int ttn = reverse ? (LL - 1 - (c * CH + i + 1)) : (c * CH + i + 1);
                size_t mn = (size_t)(b * LL + ttn) * DINNER + d;
                dln = delta[mn]; uun = u[mn]; ppn = gp[mn];
            }
            float du = dl * uu;
            float4 Bv = *(const float4*)&sBC[i][tq * 4];
            float4 Cv = *(const float4*)&sBC[i][16 + tq * 4];
            float acc;
            if (ok) {
                float p2 = pp * pp;
                float p3 = p2 * pp;
                float p4 = p2 * p2;
                float p8 = p4 * p4;
                float p12 = p8 * p4;
                float q4 = (tq == 0) ? 1.f : (tq == 1) ? p4 : (tq == 2) ? p8 : p12;
                h[0] = fmaf(q4 * pp, h[0], du * Bv.x);
                h[1] = fmaf(q4 * p2, h[1], du * Bv.y);
                h[2] = fmaf(q4 * p3, h[2], du * Bv.z);
                h[3] = fmaf(q4 * p4, h[3], du * Bv.w);
                acc = h[0] * Cv.x;
                acc = fmaf(h[1], Cv.y, acc);
                acc = fmaf(h[2], Cv.z, acc);
                acc = fmaf(h[3], Cv.w, acc);
            } else {
                float e0 = __expf(dl * A[0]);
                float e1 = __expf(dl * A[1]);
                float e2 = __expf(dl * A[2]);
                float e3 = __expf(dl * A[3]);
                h[0] = fmaf(e0, h[0], du * Bv.x);
                h[1] = fmaf(e1, h[1], du * Bv.y);
                h[2] = fmaf(e2, h[2], du * Bv.z);
                h[3] = fmaf(e3, h[3], du * Bv.w);
                acc = h[0] * Cv.x;
                acc = fmaf(h[1], Cv.y, acc);
                acc = fmaf(h[2], Cv.z, acc);
                acc = fmaf(h[3], Cv.w, acc);
            }
            acc += __shfl_xor_sync(0xffffffffu, acc, 1);
            acc += __shfl_xor_sync(0xffffffffu, acc, 2);
            if (tq == 0) sY[i][ch] = acc + uu * Dv;
            dl = dln; uu = uun; pp = ppn;
        }
        __syncthreads();
#pragma unroll
        for (int k = 0; k < (CH * 64) / 256; k++) {
            int j = tid + k * 256;
            int i = j >> 6, cc = j & 63;
            int tt = reverse ? (LL - 1 - (c * CH + i)) : (c * CH + i);
            y[(size_t)(b * LL + tt) * DINNER + d0 + cc] = sY[i][cc];
        }
    }
}

// ---------------- gate + sum both directions ---------------------------------
__global__ void combine_kernel(const float* __restrict__ xz,
                               const float* __restrict__ ya,
                               const float* __restrict__ yb,
                               float* __restrict__ yt)
{
    int idx = blockIdx.x * blockDim.x + threadIdx.x;
    if (idx >= MTOK * DINNER) return;
    int d = idx % DINNER;
    int m = idx / DINNER;
    float z = xz[(size_t)m * XZW + DINNER + d];
    yt[idx] = siluf(z) * (ya[idx] + yb[idx]);
}

// ---------------- launch -----------------------------------------------------
extern "C" void kernel_launch(void* const* d_in, const int* in_sizes, int n_in,
                              void* d_out, int out_size)
{
    const float* x       = (const float*)d_in[0];
    const float* in_w    = (const float*)d_in[1];
    const float* out_w   = (const float*)d_in[2];
    const float* conv_wf = (const float*)d_in[3];
    const float* conv_bf = (const float*)d_in[4];
    const float* xproj_f = (const float*)d_in[5];
    const float* dt_wf   = (const float*)d_in[6];
    const float* dt_bf   = (const float*)d_in[7];
    const float* alog_f  = (const float*)d_in[8];
    const float* D_f     = (const float*)d_in[9];
    const float* conv_wr = (const float*)d_in[10];
    const float* conv_br = (const float*)d_in[11];
    const float* xproj_r = (const float*)d_in[12];
    const float* dt_wr   = (const float*)d_in[13];
    const float* dt_br   = (const float*)d_in[14];
    const float* alog_r  = (const float*)d_in[15];
    const float* D_r     = (const float*)d_in[16];

    float *xz, *u0, *u1, *xd0, *xd1, *de0, *de1, *p0, *p1, *y0, *y1, *yt;
    cudaGetSymbolAddress((void**)&xz,  g_xz);
    cudaGetSymbolAddress((void**)&u0,  g_u0);
    cudaGetSymbolAddress((void**)&u1,  g_u1);
    cudaGetSymbolAddress((void**)&xd0, g_xd0);
    cudaGetSymbolAddress((void**)&xd1, g_xd1);
    cudaGetSymbolAddress((void**)&de0, g_de0);
    cudaGetSymbolAddress((void**)&de1, g_de1);
    cudaGetSymbolAddress((void**)&p0,  g_p0);
    cudaGetSymbolAddress((void**)&p1,  g_p1);
    cudaGetSymbolAddress((void**)&y0,  g_y0);
    cudaGetSymbolAddress((void**)&y1,  g_y1);
    cudaGetSymbolAddress((void**)&yt,  g_yt);

    float* out = (float*)d_out;

    // zero-init for split-K atomic outputs
    zero_kernel<<<(MTOK * XDBLW + 255) / 256, 256>>>(xd0, MTOK * XDBLW);
    zero_kernel<<<(MTOK * XDBLW + 255) / 256, 256>>>(xd1, MTOK * XDBLW);
    zero_kernel<<<(MTOK * DMODEL + 255) / 256, 256>>>(out, MTOK * DMODEL);

    // 1) xz = x @ in_proj_w^T   (2048 x 3072, K=768), shared by both dirs
    {
        dim3 grid(XZW / 128, MTOK / 128, 1);
        gemm_tc<0, 0><<<grid, 256>>>(x, x, in_w, in_w, xz, xz,
                                     nullptr, nullptr, nullptr, nullptr,
                                     nullptr, nullptr,
                                     MTOK, XZW, DMODEL, DMODEL, DMODEL, XZW, 1);
    }
    // 2) depthwise conv + silu, both directions
    {
        int n = MTOK * DINNER;
        conv_silu_kernel<<<(n + 255) / 256, 256>>>(xz, conv_wf, conv_bf,
                                                   conv_wr, conv_br, u0, u1);
    }
    // 3) x_dbl = u @ x_proj_w^T  (2048 x 80, K=1536), both dirs, split-K=4
    {
        dim3 grid(1, MTOK / 128, 2 * 4);
        gemm_tc<0, 1><<<grid, 256>>>(u0, u1, xproj_f, xproj_r, xd0, xd1,
                                     nullptr, nullptr, nullptr, nullptr,
                                     nullptr, nullptr,
                                     MTOK, XDBLW, DINNER / 4, DINNER, DINNER, XDBLW, 4);
    }
    // 4) delta = softplus(dt @ dt_w^T + dt_b), + p = exp(delta*A0), batched dirs
    {
        dim3 grid(DINNER / 128, MTOK / 128, 2);
        gemm_tc<1, 0><<<grid, 256>>>(xd0, xd1, dt_wf, dt_wr, de0, de1,
                                     dt_bf, dt_br, p0, p1,
                                     alog_f, alog_r,
                                     MTOK, DINNER, DTRANK, XDBLW, DTRANK, DINNER, 1);
    }
    // 5) selective scans, both directions, 4 threads/channel
    {
        dim3 grid(DINNER / 64, BB, 2);
        scan4_kernel<<<grid, 256>>>(de0, de1, p0, p1, xd0, xd1, u0, u1,
                                    alog_f, alog_r, D_f, D_r, y0, y1);
    }
    // 6) gate + sum
    {
        int n = MTOK * DINNER;
        combine_kernel<<<(n + 255) / 256, 256>>>(xz, y0, y1, yt);
    }
    // 7) out = y_tot @ out_proj_w^T  (2048 x 768, K=1536), split-K=2
    {
        dim3 grid(DMODEL / 128, MTOK / 128, 2);
        gemm_tc<0, 1><<<grid, 256>>>(yt, yt, out_w, out_w, out, out,
                                     nullptr, nullptr, nullptr, nullptr,
                                     nullptr, nullptr,
                                     MTOK, DMODEL, DINNER / 2, DINNER, DINNER, DMODEL, 2);
    }
}

// round 7
// speedup vs baseline: 3.2405x; 1.2809x over previous
#include <cuda_runtime.h>
#include <cuda_bf16.h>
#include <math.h>
#include <stdint.h>

// Problem constants
#define BB 2
#define LL 1024
#define DMODEL 768
#define DINNER 1536
#define DSTATE 16
#define DCONV 4
#define DTRANK 48
#define MTOK (BB*LL)              // 2048 token rows
#define XZW (2*DINNER)            // 3072
#define XDBLW (DTRANK + 2*DSTATE) // 80

// ---------------- scratch (device globals; no allocation allowed) ------------
__device__ float g_xz[MTOK * XZW];
__device__ float g_u0[MTOK * DINNER];
__device__ float g_u1[MTOK * DINNER];
__device__ float g_xd0[MTOK * XDBLW];
__device__ float g_xd1[MTOK * XDBLW];
__device__ float g_de0[MTOK * DINNER];
__device__ float g_de1[MTOK * DINNER];
__device__ float g_p0[MTOK * DINNER];   // exp(delta*A0) forward
__device__ float g_p1[MTOK * DINNER];   // exp(delta*A0) reverse
__device__ float g_y0[MTOK * DINNER];
__device__ float g_y1[MTOK * DINNER];
__device__ float g_yt[MTOK * DINNER];

__device__ __forceinline__ float siluf(float x) {
    return x / (1.f + __expf(-x));
}
__device__ __forceinline__ float softplusf(float x) {
    return (x > 20.f) ? x : log1pf(__expf(x));
}
__device__ __forceinline__ float tf32r(float x) {
    uint32_t u;
    asm("cvt.rna.tf32.f32 %0, %1;" : "=r"(u) : "f"(x));
    return __uint_as_float(u);
}
__device__ __forceinline__ void mma_tf32(float c[4],
                                         uint32_t a0, uint32_t a1, uint32_t a2, uint32_t a3,
                                         uint32_t b0, uint32_t b1) {
    asm volatile(
        "mma.sync.aligned.m16n8k8.row.col.f32.tf32.tf32.f32 "
        "{%0,%1,%2,%3}, {%4,%5,%6,%7}, {%8,%9}, {%0,%1,%2,%3};"
        : "+f"(c[0]), "+f"(c[1]), "+f"(c[2]), "+f"(c[3])
        : "r"(a0), "r"(a1), "r"(a2), "r"(a3), "r"(b0), "r"(b1));
}

// ---------------- tf32 tensor-core NT GEMM, fragment-layout smem -------------
// (unchanged from R6 — known good; R8 target)
template<int EPI, int SPLIT>
__global__ __launch_bounds__(256)
void gemm_tc(const float* __restrict__ A0p, const float* __restrict__ A1p,
             const float* __restrict__ W0p, const float* __restrict__ W1p,
             float* __restrict__ C0p, float* __restrict__ C1p,
             const float* __restrict__ b0p, const float* __restrict__ b1p,
             float* __restrict__ P0p, float* __restrict__ P1p,
             const float* __restrict__ al0, const float* __restrict__ al1,
             int M, int N, int Kc,
             int lda, int ldw, int ldc, int ksplit)
{
    const int dir = blockIdx.z / ksplit;
    const int kch = blockIdx.z % ksplit;
    const float* __restrict__ A    = dir ? A1p : A0p;
    const float* __restrict__ W    = dir ? W1p : W0p;
    float* __restrict__ C          = dir ? C1p : C0p;
    const float* __restrict__ bias = dir ? b1p : b0p;
    float* __restrict__ P          = dir ? P1p : P0p;
    const float* __restrict__ alog = dir ? al1 : al0;

    __shared__ float As[2][2048];
    __shared__ float Bs[2][2048];
    __shared__ float sA0[128];

    const int tid  = threadIdx.x;
    const int warp = tid >> 5, lane = tid & 31;
    const int wm = warp & 3, wn = warp >> 2;
    const int gid = lane >> 2, tg = lane & 3;
    const int m0 = blockIdx.y * 128, n0 = blockIdx.x * 128;
    const int kbeg = kch * Kc;

    if (EPI == 1 && tid < 128) {
        int cc = n0 + tid;
        sA0[tid] = (cc < N) ? -__expf(alog[(size_t)cc * DSTATE]) : 0.f;
    }

    const float* aptr[2]; int asts[2];
#pragma unroll
    for (int j = 0; j < 2; j++) {
        int f = tid + j * 256;
        int ks = f >> 8, mw = (f >> 5) & 7, ln = f & 31;
        int g = ln >> 2, t4 = ln & 3;
        aptr[j] = A + (size_t)(m0 + mw * 16 + g) * lda + kbeg + ks * 8 + t4;
        asts[j] = ((ks * 8 + mw) * 32 + ln) * 4;
    }
    const float* bptr[4]; int bsts[4]; bool bok[4];
#pragma unroll
    for (int j = 0; j < 4; j++) {
        int f = tid + j * 256;
        int ks = f >> 9, nw = (f >> 5) & 15, ln = f & 31;
        int g = ln >> 2, t4 = ln & 3;
        int n = n0 + nw * 8 + g;
        bok[j] = (n < N);
        bptr[j] = W + (size_t)(bok[j] ? n : 0) * ldw + kbeg + ks * 8 + t4;
        bsts[j] = ((ks * 16 + nw) * 32 + ln) * 2;
    }

    float4 ar[2];
    float2 br[4];
#pragma unroll
    for (int j = 0; j < 2; j++) {
        const float* p = aptr[j];
        ar[j] = make_float4(tf32r(__ldg(p)),     tf32r(__ldg(p + 8 * lda)),
                            tf32r(__ldg(p + 4)), tf32r(__ldg(p + 8 * lda + 4)));
    }
#pragma unroll
    for (int j = 0; j < 4; j++) {
        const float* p = bptr[j];
        br[j].x = bok[j] ? tf32r(__ldg(p))     : 0.f;
        br[j].y = bok[j] ? tf32r(__ldg(p + 4)) : 0.f;
    }
#pragma unroll
    for (int j = 0; j < 2; j++) *(float4*)&As[0][asts[j]] = ar[j];
#pragma unroll
    for (int j = 0; j < 4; j++) *(float2*)&Bs[0][bsts[j]] = br[j];
    __syncthreads();

    float acc[2][8][4];
#pragma unroll
    for (int mt = 0; mt < 2; mt++)
#pragma unroll
        for (int nt = 0; nt < 8; nt++)
#pragma unroll
            for (int r = 0; r < 4; r++) acc[mt][nt][r] = 0.f;

    const int nk = Kc / 16;
    for (int i = 0; i < nk; i++) {
        int cur = i & 1;
        if (i + 1 < nk) {
#pragma unroll
            for (int j = 0; j < 2; j++) {
                aptr[j] += 16;
                const float* p = aptr[j];
                ar[j] = make_float4(tf32r(__ldg(p)),     tf32r(__ldg(p + 8 * lda)),
                                    tf32r(__ldg(p + 4)), tf32r(__ldg(p + 8 * lda + 4)));
            }
#pragma unroll
            for (int j = 0; j < 4; j++) {
                bptr[j] += 16;
                const float* p = bptr[j];
                br[j].x = bok[j] ? tf32r(__ldg(p))     : 0.f;
                br[j].y = bok[j] ? tf32r(__ldg(p + 4)) : 0.f;
            }
        }
#pragma unroll
        for (int ks = 0; ks < 2; ks++) {
            float4 af[2];
            float2 bf[8];
#pragma unroll
            for (int mt = 0; mt < 2; mt++)
                af[mt] = *(const float4*)&As[cur][((ks * 8 + wm * 2 + mt) * 32 + lane) * 4];
#pragma unroll
            for (int nt = 0; nt < 8; nt++)
                bf[nt] = *(const float2*)&Bs[cur][((ks * 16 + wn * 8 + nt) * 32 + lane) * 2];
#pragma unroll
            for (int mt = 0; mt < 2; mt++)
#pragma unroll
                for (int nt = 0; nt < 8; nt++)
                    mma_tf32(acc[mt][nt],
                             __float_as_uint(af[mt].x), __float_as_uint(af[mt].y),
                             __float_as_uint(af[mt].z), __float_as_uint(af[mt].w),
                             __float_as_uint(bf[nt].x), __float_as_uint(bf[nt].y));
        }
        if (i + 1 < nk) {
            int nxt = (i + 1) & 1;
#pragma unroll
            for (int j = 0; j < 2; j++) *(float4*)&As[nxt][asts[j]] = ar[j];
#pragma unroll
            for (int j = 0; j < 4; j++) *(float2*)&Bs[nxt][bsts[j]] = br[j];
            __syncthreads();
        }
    }

#pragma unroll
    for (int mt = 0; mt < 2; mt++) {
        int r0 = m0 + wm * 32 + mt * 16 + gid;
#pragma unroll
        for (int nt = 0; nt < 8; nt++) {
            int cc = n0 + wn * 64 + nt * 8 + tg * 2;
#pragma unroll
            for (int jj = 0; jj < 2; jj++) {
                int gn = cc + jj;
                if (gn >= N) continue;
                float v0 = acc[mt][nt][jj];
                float v1 = acc[mt][nt][2 + jj];
                if (EPI == 1) {
                    float bv = bias[gn];
                    float a0 = sA0[gn - n0];
                    float d0 = softplusf(v0 + bv);
                    float d1 = softplusf(v1 + bv);
                    C[(size_t)r0 * ldc + gn]       = d0;
                    C[(size_t)(r0 + 8) * ldc + gn] = d1;
                    P[(size_t)r0 * ldc + gn]       = __expf(d0 * a0);
                    P[(size_t)(r0 + 8) * ldc + gn] = __expf(d1 * a0);
                } else if (SPLIT == 1) {
                    atomicAdd(&C[(size_t)r0 * ldc + gn], v0);
                    atomicAdd(&C[(size_t)(r0 + 8) * ldc + gn], v1);
                } else {
                    C[(size_t)r0 * ldc + gn]       = v0;
                    C[(size_t)(r0 + 8) * ldc + gn] = v1;
                }
            }
        }
    }
}

// ---------------- zero-init ---------------------------------------------------
__global__ void zero_kernel(float* __restrict__ p, int n)
{
    int i = blockIdx.x * blockDim.x + threadIdx.x;
    if (i < n) p[i] = 0.f;
}

// ------ depthwise causal (fwd) + anti-causal (rev) conv + silu, float4 -------
__global__ void conv_silu_kernel(const float* __restrict__ xz,
                                 const float* __restrict__ wf, const float* __restrict__ bf,
                                 const float* __restrict__ wr, const float* __restrict__ br,
                                 float* __restrict__ uf, float* __restrict__ ur)
{
    int v = blockIdx.x * blockDim.x + threadIdx.x;
    const int ND4 = DINNER / 4;
    if (v >= MTOK * ND4) return;
    int d4 = v % ND4;
    int t  = (v / ND4) % LL;
    int b  = v / (ND4 * LL);
    int d  = d4 * 4;

    const float* base = xz + (size_t)b * LL * XZW + d;

    // conv weights: [channel][tap]; 4 channels = 4 float4
    float4 Wf[4], Wr[4];
#pragma unroll
    for (int j = 0; j < 4; j++) {
        Wf[j] = *(const float4*)&wf[(d + j) * DCONV];
        Wr[j] = *(const float4*)&wr[(d + j) * DCONV];
    }
    float4 accf = *(const float4*)&bf[d];
    float4 accr = *(const float4*)&br[d];

#pragma unroll
    for (int k = 0; k < DCONV; k++) {
        int tf = t - (DCONV - 1) + k;
        int tr = t + (DCONV - 1) - k;
        float4 vf = (tf >= 0) ? *(const float4*)(base + (size_t)tf * XZW)
                              : make_float4(0.f, 0.f, 0.f, 0.f);
        float4 vr = (tr < LL) ? *(const float4*)(base + (size_t)tr * XZW)
                              : make_float4(0.f, 0.f, 0.f, 0.f);
        const float wfk[4] = { ((const float*)&Wf[0])[k], ((const float*)&Wf[1])[k],
                               ((const float*)&Wf[2])[k], ((const float*)&Wf[3])[k] };
        const float wrk[4] = { ((const float*)&Wr[0])[k], ((const float*)&Wr[1])[k],
                               ((const float*)&Wr[2])[k], ((const float*)&Wr[3])[k] };
        accf.x = fmaf(wfk[0], vf.x, accf.x);
        accf.y = fmaf(wfk[1], vf.y, accf.y);
        accf.z = fmaf(wfk[2], vf.z, accf.z);
        accf.w = fmaf(wfk[3], vf.w, accf.w);
        accr.x = fmaf(wrk[0], vr.x, accr.x);
        accr.y = fmaf(wrk[1], vr.y, accr.y);
        accr.z = fmaf(wrk[2], vr.z, accr.z);
        accr.w = fmaf(wrk[3], vr.w, accr.w);
    }
    size_t o = (size_t)(b * LL + t) * DINNER + d;
    *(float4*)&uf[o] = make_float4(siluf(accf.x), siluf(accf.y), siluf(accf.z), siluf(accf.w));
    *(float4*)&ur[o] = make_float4(siluf(accr.x), siluf(accr.y), siluf(accr.z), siluf(accr.w));
}

// ---------------- selective scan, smem-staged ---------------------------------
// 128 threads = 32 channels x 4 threads (4 states each). Chunks of SCH=32
// timesteps: p/delta/u/B/C staged into shared memory with coalesced float4
// loads (latency off the serial path), serial loop reads smem with 1-step
// register prefetch. grid = (DINNER/32, BB, 2dirs) = 192 blocks.
#define SCH  32
#define SCHN 32
__global__ __launch_bounds__(128)
void scan_kernel(const float* __restrict__ de0p, const float* __restrict__ de1p,
                 const float* __restrict__ gp0,  const float* __restrict__ gp1,
                 const float* __restrict__ xd0p, const float* __restrict__ xd1p,
                 const float* __restrict__ u0p,  const float* __restrict__ u1p,
                 const float* __restrict__ alf,  const float* __restrict__ alr,
                 const float* __restrict__ Dfp,  const float* __restrict__ Drp,
                 float* __restrict__ y0p, float* __restrict__ y1p)
{
    const int reverse = blockIdx.z;
    const float* __restrict__ delta = reverse ? de1p : de0p;
    const float* __restrict__ gp    = reverse ? gp1  : gp0;
    const float* __restrict__ xdbl  = reverse ? xd1p : xd0p;
    const float* __restrict__ u     = reverse ? u1p  : u0p;
    const float* __restrict__ A_log = reverse ? alr  : alf;
    const float* __restrict__ Dp    = reverse ? Drp  : Dfp;
    float* __restrict__ y           = reverse ? y1p  : y0p;

    __shared__ float sBC[SCH][32];     // B[0..15], C[16..31] per step
    __shared__ float sP [SCH][SCHN];
    __shared__ float sDL[SCH][SCHN];
    __shared__ float sU [SCH][SCHN];
    __shared__ float sY [SCH][SCHN];

    const int tid = threadIdx.x;               // 0..127
    const int ch = tid >> 2, tq = tid & 3;     // channel, quad-thread
    const int lane = tid & 31;
    const int d0 = blockIdx.x * SCHN;
    const int d = d0 + ch;
    const int b = blockIdx.y;

    float A[4];
#pragma unroll
    for (int j = 0; j < 4; j++)
        A[j] = -__expf(A_log[(size_t)d * DSTATE + tq * 4 + j]);
    float A0 = -__expf(A_log[(size_t)d * DSTATE]);
    bool okl = true;
#pragma unroll
    for (int j = 0; j < 4; j++) {
        float t = (float)(tq * 4 + j + 1) * A0;
        okl = okl && (fabsf(A[j] - t) <= 1e-3f * fabsf(A[j]) + 1e-6f);
    }
    unsigned bal = __ballot_sync(0xffffffffu, okl);
    int qsh = lane & 28;
    bool ok = ((bal >> qsh) & 0xFu) == 0xFu;
    float Dv = Dp[d];

    float h[4] = {0.f, 0.f, 0.f, 0.f};

    for (int c = 0; c < LL / SCH; c++) {
        __syncthreads();
        // stage this chunk: 256 float4 per array, 2 per thread, coalesced rows
#pragma unroll
        for (int k = 0; k < 2; k++) {
            int fi = tid + k * 128;            // 0..255
            int i  = fi >> 3;                  // step in chunk
            int qq = fi & 7;                   // float4 within 32-wide row
            int tt = reverse ? (LL - 1 - (c * SCH + i)) : (c * SCH + i);
            size_t rb = (size_t)(b * LL + tt) * DINNER + d0 + qq * 4;
            *(float4*)&sP [i][qq * 4] = *(const float4*)&gp[rb];
            *(float4*)&sDL[i][qq * 4] = *(const float4*)&delta[rb];
            *(float4*)&sU [i][qq * 4] = *(const float4*)&u[rb];
            *(float4*)&sBC[i][qq * 4] =
                *(const float4*)&xdbl[(size_t)(b * LL + tt) * XDBLW + DTRANK + qq * 4];
        }
        __syncthreads();

        float pp = sP[0][ch], dl = sDL[0][ch], uu = sU[0][ch];
        float4 Bv = *(const float4*)&sBC[0][tq * 4];
        float4 Cv = *(const float4*)&sBC[0][16 + tq * 4];

        for (int i = 0; i < SCH; i++) {
            float ppn = 0.f, dln = 0.f, uun = 0.f;
            float4 Bn = Bv, Cn = Cv;
            if (i + 1 < SCH) {
                ppn = sP[i + 1][ch]; dln = sDL[i + 1][ch]; uun = sU[i + 1][ch];
                Bn = *(const float4*)&sBC[i + 1][tq * 4];
                Cn = *(const float4*)&sBC[i + 1][16 + tq * 4];
            }
            float du = dl * uu;
            float acc;
            if (ok) {
                float p2 = pp * pp;
                float p3 = p2 * pp;
                float p4 = p2 * p2;
                float p8 = p4 * p4;
                float p12 = p8 * p4;
                float q4 = (tq == 0) ? 1.f : (tq == 1) ? p4 : (tq == 2) ? p8 : p12;
                h[0] = fmaf(q4 * pp, h[0], du * Bv.x);
                h[1] = fmaf(q4 * p2, h[1], du * Bv.y);
                h[2] = fmaf(q4 * p3, h[2], du * Bv.z);
                h[3] = fmaf(q4 * p4, h[3], du * Bv.w);
            } else {
                h[0] = fmaf(__expf(dl * A[0]), h[0], du * Bv.x);
                h[1] = fmaf(__expf(dl * A[1]), h[1], du * Bv.y);
                h[2] = fmaf(__expf(dl * A[2]), h[2], du * Bv.z);
                h[3] = fmaf(__expf(dl * A[3]), h[3], du * Bv.w);
            }
            acc = h[0] * Cv.x;
            acc = fmaf(h[1], Cv.y, acc);
            acc = fmaf(h[2], Cv.z, acc);
            acc = fmaf(h[3], Cv.w, acc);
            acc += __shfl_xor_sync(0xffffffffu, acc, 1);
            acc += __shfl_xor_sync(0xffffffffu, acc, 2);
            if (tq == 0) sY[i][ch] = acc + uu * Dv;
            pp = ppn; dl = dln; uu = uun; Bv = Bn; Cv = Cn;
        }
        __syncthreads();
        // writeback: coalesced float4 rows
#pragma unroll
        for (int k = 0; k < 2; k++) {
            int fi = tid + k * 128;
            int i  = fi >> 3;
            int qq = fi & 7;
            int tt = reverse ? (LL - 1 - (c * SCH + i)) : (c * SCH + i);
            *(float4*)&y[(size_t)(b * LL + tt) * DINNER + d0 + qq * 4] =
                *(const float4*)&sY[i][qq * 4];
        }
    }
}

// ---------------- gate + sum both directions, float4 --------------------------
__global__ void combine_kernel(const float* __restrict__ xz,
                               const float* __restrict__ ya,
                               const float* __restrict__ yb,
                               float* __restrict__ yt)
{
    int v = blockIdx.x * blockDim.x + threadIdx.x;
    const int ND4 = DINNER / 4;
    if (v >= MTOK * ND4) return;
    int d4 = v % ND4;
    int m  = v / ND4;
    float4 z  = *(const float4*)&xz[(size_t)m * XZW + DINNER + d4 * 4];
    float4 a  = *(const float4*)&ya[(size_t)m * DINNER + d4 * 4];
    float4 bb = *(const float4*)&yb[(size_t)m * DINNER + d4 * 4];
    float4 o;
    o.x = siluf(z.x) * (a.x + bb.x);
    o.y = siluf(z.y) * (a.y + bb.y);
    o.z = siluf(z.z) * (a.z + bb.z);
    o.w = siluf(z.w) * (a.w + bb.w);
    *(float4*)&yt[(size_t)m * DINNER + d4 * 4] = o;
}

// ---------------- launch -----------------------------------------------------
extern "C" void kernel_launch(void* const* d_in, const int* in_sizes, int n_in,
                              void* d_out, int out_size)
{
    const float* x       = (const float*)d_in[0];
    const float* in_w    = (const float*)d_in[1];
    const float* out_w   = (const float*)d_in[2];
    const float* conv_wf = (const float*)d_in[3];
    const float* conv_bf = (const float*)d_in[4];
    const float* xproj_f = (const float*)d_in[5];
    const float* dt_wf   = (const float*)d_in[6];
    const float* dt_bf   = (const float*)d_in[7];
    const float* alog_f  = (const float*)d_in[8];
    const float* D_f     = (const float*)d_in[9];
    const float* conv_wr = (const float*)d_in[10];
    const float* conv_br = (const float*)d_in[11];
    const float* xproj_r = (const float*)d_in[12];
    const float* dt_wr   = (const float*)d_in[13];
    const float* dt_br   = (const float*)d_in[14];
    const float* alog_r  = (const float*)d_in[15];
    const float* D_r     = (const float*)d_in[16];

    float *xz, *u0, *u1, *xd0, *xd1, *de0, *de1, *p0, *p1, *y0, *y1, *yt;
    cudaGetSymbolAddress((void**)&xz,  g_xz);
    cudaGetSymbolAddress((void**)&u0,  g_u0);
    cudaGetSymbolAddress((void**)&u1,  g_u1);
    cudaGetSymbolAddress((void**)&xd0, g_xd0);
    cudaGetSymbolAddress((void**)&xd1, g_xd1);
    cudaGetSymbolAddress((void**)&de0, g_de0);
    cudaGetSymbolAddress((void**)&de1, g_de1);
    cudaGetSymbolAddress((void**)&p0,  g_p0);
    cudaGetSymbolAddress((void**)&p1,  g_p1);
    cudaGetSymbolAddress((void**)&y0,  g_y0);
    cudaGetSymbolAddress((void**)&y1,  g_y1);
    cudaGetSymbolAddress((void**)&yt,  g_yt);

    float* out = (float*)d_out;

    // zero-init for split-K atomic outputs
    zero_kernel<<<(MTOK * XDBLW + 255) / 256, 256>>>(xd0, MTOK * XDBLW);
    zero_kernel<<<(MTOK * XDBLW + 255) / 256, 256>>>(xd1, MTOK * XDBLW);
    zero_kernel<<<(MTOK * DMODEL + 255) / 256, 256>>>(out, MTOK * DMODEL);

    // 1) xz = x @ in_proj_w^T   (2048 x 3072, K=768), shared by both dirs
    {
        dim3 grid(XZW / 128, MTOK / 128, 1);
        gemm_tc<0, 0><<<grid, 256>>>(x, x, in_w, in_w, xz, xz,
                                     nullptr, nullptr, nullptr, nullptr,
                                     nullptr, nullptr,
                                     MTOK, XZW, DMODEL, DMODEL, DMODEL, XZW, 1);
    }
    // 2) depthwise conv + silu, both directions, float4
    {
        int n = MTOK * (DINNER / 4);
        conv_silu_kernel<<<(n + 255) / 256, 256>>>(xz, conv_wf, conv_bf,
                                                   conv_wr, conv_br, u0, u1);
    }
    // 3) x_dbl = u @ x_proj_w^T  (2048 x 80, K=1536), both dirs, split-K=4
    {
        dim3 grid(1, MTOK / 128, 2 * 4);
        gemm_tc<0, 1><<<grid, 256>>>(u0, u1, xproj_f, xproj_r, xd0, xd1,
                                     nullptr, nullptr, nullptr, nullptr,
                                     nullptr, nullptr,
                                     MTOK, XDBLW, DINNER / 4, DINNER, DINNER, XDBLW, 4);
    }
    // 4) delta = softplus(dt @ dt_w^T + dt_b), + p = exp(delta*A0), batched dirs
    {
        dim3 grid(DINNER / 128, MTOK / 128, 2);
        gemm_tc<1, 0><<<grid, 256>>>(xd0, xd1, dt_wf, dt_wr, de0, de1,
                                     dt_bf, dt_br, p0, p1,
                                     alog_f, alog_r,
                                     MTOK, DINNER, DTRANK, XDBLW, DTRANK, DINNER, 1);
    }
    // 5) selective scans, smem-staged, 192 blocks
    {
        dim3 grid(DINNER / SCHN, BB, 2);
        scan_kernel<<<grid, 128>>>(de0, de1, p0, p1, xd0, xd1, u0, u1,
                                   alog_f, alog_r, D_f, D_r, y0, y1);
    }
    // 6) gate + sum, float4
    {
        int n = MTOK * (DINNER / 4);
        combine_kernel<<<(n + 255) / 256, 256>>>(xz, y0, y1, yt);
    }
    // 7) out = y_tot @ out_proj_w^T  (2048 x 768, K=1536), split-K=2
    {
        dim3 grid(DMODEL / 128, MTOK / 128, 2);
        gemm_tc<0, 1><<<grid, 256>>>(yt, yt, out_w, out_w, out, out,
                                     nullptr, nullptr, nullptr, nullptr,
                                     nullptr, nullptr,
                                     MTOK, DMODEL, DINNER / 2, DINNER, DINNER, DMODEL, 2);
    }
}

// round 8
// speedup vs baseline: 3.7077x; 1.1442x over previous
#include <cuda_runtime.h>
#include <cuda_bf16.h>
#include <math.h>
#include <stdint.h>

// Problem constants
#define BB 2
#define LL 1024
#define DMODEL 768
#define DINNER 1536
#define DSTATE 16
#define DCONV 4
#define DTRANK 48
#define MTOK (BB*LL)              // 2048 token rows
#define XZW (2*DINNER)            // 3072
#define XDBLW (DTRANK + 2*DSTATE) // 80

// ---------------- scratch (device globals; no allocation allowed) ------------
__device__ float g_xz[MTOK * XZW];
__device__ float g_u0[MTOK * DINNER];
__device__ float g_u1[MTOK * DINNER];
__device__ float g_xd0[MTOK * XDBLW];
__device__ float g_xd1[MTOK * XDBLW];
__device__ float g_de0[MTOK * DINNER];
__device__ float g_de1[MTOK * DINNER];
__device__ float g_p0[MTOK * DINNER];
__device__ float g_p1[MTOK * DINNER];
__device__ float g_y0[MTOK * DINNER];
__device__ float g_y1[MTOK * DINNER];
__device__ float g_yt[MTOK * DINNER];
// tf32-pre-rounded weight copies
__device__ float g_win [XZW * DMODEL];
__device__ float g_wout[DMODEL * DINNER];
__device__ float g_wx0 [XDBLW * DINNER];
__device__ float g_wx1 [XDBLW * DINNER];
__device__ float g_wd0 [DINNER * DTRANK];
__device__ float g_wd1 [DINNER * DTRANK];

__device__ __forceinline__ float siluf(float x) {
    return x / (1.f + __expf(-x));
}
__device__ __forceinline__ float softplusf(float x) {
    return (x > 20.f) ? x : log1pf(__expf(x));
}
__device__ __forceinline__ float tf32r(float x) {
    uint32_t u;
    asm("cvt.rna.tf32.f32 %0, %1;" : "=r"(u) : "f"(x));
    return __uint_as_float(u);
}
__device__ __forceinline__ void mma_tf32(float c[4],
                                         uint32_t a0, uint32_t a1, uint32_t a2, uint32_t a3,
                                         uint32_t b0, uint32_t b1) {
    asm volatile(
        "mma.sync.aligned.m16n8k8.row.col.f32.tf32.tf32.f32 "
        "{%0,%1,%2,%3}, {%4,%5,%6,%7}, {%8,%9}, {%0,%1,%2,%3};"
        : "+f"(c[0]), "+f"(c[1]), "+f"(c[2]), "+f"(c[3])
        : "r"(a0), "r"(a1), "r"(a2), "r"(a3), "r"(b0), "r"(b1));
}
__device__ __forceinline__ void cp_async16(uint32_t saddr, const void* g, int bytes) {
    asm volatile("cp.async.cg.shared.global [%0], [%1], 16, %2;"
                 :: "r"(saddr), "l"(g), "r"(bytes));
}
__device__ __forceinline__ void cp_commit() {
    asm volatile("cp.async.commit_group;");
}
template<int PEND>
__device__ __forceinline__ void cp_wait() {
    asm volatile("cp.async.wait_group %0;" :: "n"(PEND));
}

// ---------------- tf32 tensor-core NT GEMM, cp.async + XOR swizzle ----------
// C[m,n] = sum_k A[m,k] * W[n,k].  BM=128, BN=128, BK=32, 256 threads.
// 8 warps: wm = warp&3 (32 rows), wn = warp>>2 (64 cols); per warp per k8:
// 2(mt) x 8(nt) m16n8k8 MMAs. Smem tiles row-major 128x32 with XOR swizzle
// (slot ^ (row&7)); staged by cp.async (full 128B rows), double-buffered.
// W must be PRE-ROUNDED to tf32; A is rounded at fragment read.
// K tail & N tail (rows >= N) are zero-filled via cp.async src-size 0.
// blockIdx.z = dir*ksplit + kchunk.  EPI=1: softplus+bias, P=exp(d*A0).
// SPLIT=1: atomicAdd into pre-zeroed C.
template<int EPI, int SPLIT>
__global__ __launch_bounds__(256)
void gemm_tc(const float* __restrict__ A0p, const float* __restrict__ A1p,
             const float* __restrict__ W0p, const float* __restrict__ W1p,
             float* __restrict__ C0p, float* __restrict__ C1p,
             const float* __restrict__ b0p, const float* __restrict__ b1p,
             float* __restrict__ P0p, float* __restrict__ P1p,
             const float* __restrict__ al0, const float* __restrict__ al1,
             int M, int N, int Kc,
             int lda, int ldw, int ldc, int ksplit)
{
    const int dir = blockIdx.z / ksplit;
    const int kch = blockIdx.z % ksplit;
    const float* __restrict__ A    = dir ? A1p : A0p;
    const float* __restrict__ W    = dir ? W1p : W0p;
    float* __restrict__ C          = dir ? C1p : C0p;
    const float* __restrict__ bias = dir ? b1p : b0p;
    float* __restrict__ P          = dir ? P1p : P0p;
    const float* __restrict__ alog = dir ? al1 : al0;

    extern __shared__ float smem[];
    float* As[2] = { smem,         smem + 4096 };
    float* Bs[2] = { smem + 8192,  smem + 12288 };
    float* sA0   = smem + 16384;                    // EPI1 only (128 floats)
    uint32_t sbase = (uint32_t)__cvta_generic_to_shared(smem);

    const int tid  = threadIdx.x;
    const int warp = tid >> 5, lane = tid & 31;
    const int wm = warp & 3, wn = warp >> 2;
    const int gid = lane >> 2, tg = lane & 3;
    const int m0 = blockIdx.y * 128, n0 = blockIdx.x * 128;
    const int kbeg = kch * Kc;

    if (EPI == 1 && tid < 128) {
        int cc = n0 + tid;
        sA0[tid] = (cc < N) ? -__expf(alog[(size_t)cc * DSTATE]) : 0.f;
    }

    // staging descriptors: 4 slots each for A and B per thread
    const float* aptr[4]; uint32_t aoff[4];
    const float* bptr[4]; uint32_t boff[4];
    int  kslot[4];  bool bokk[4];
#pragma unroll
    for (int i = 0; i < 4; i++) {
        int f = tid + i * 256;              // 0..1023
        int row = f >> 3, slot = f & 7;
        kslot[i] = slot * 4;
        uint32_t soff = (uint32_t)(row * 32 + (slot ^ (row & 7)) * 4) * 4u;
        aoff[i] = soff;
        boff[i] = soff;
        aptr[i] = A + (size_t)(m0 + row) * lda + kbeg + slot * 4;
        int brow = n0 + row;
        bokk[i] = (brow < N);
        if (brow >= N) brow = N - 1;
        bptr[i] = W + (size_t)brow * ldw + kbeg + slot * 4;
    }

    const int nk = (Kc + 31) / 32;

    // stage chunk 0
#pragma unroll
    for (int i = 0; i < 4; i++) {
        bool vk = kslot[i] < Kc;
        cp_async16(sbase + aoff[i],           aptr[i], vk ? 16 : 0);
        cp_async16(sbase + 32768u + boff[i],  bptr[i], (vk && bokk[i]) ? 16 : 0);
    }
    cp_commit();

    float acc[2][8][4];
#pragma unroll
    for (int mt = 0; mt < 2; mt++)
#pragma unroll
        for (int nt = 0; nt < 8; nt++)
#pragma unroll
            for (int r = 0; r < 4; r++) acc[mt][nt][r] = 0.f;

    for (int ch = 0; ch < nk; ch++) {
        int cur = ch & 1;
        if (ch + 1 < nk) {
            int kc = (ch + 1) * 32;
            uint32_t sa = sbase + (uint32_t)((ch + 1) & 1) * 16384u;
            uint32_t sb = sa + 32768u;
#pragma unroll
            for (int i = 0; i < 4; i++) {
                bool vk = (kc + kslot[i]) < Kc;
                cp_async16(sa + aoff[i], aptr[i] + kc, vk ? 16 : 0);
                cp_async16(sb + boff[i], bptr[i] + kc, (vk && bokk[i]) ? 16 : 0);
            }
            cp_commit();
            cp_wait<1>();
        } else {
            cp_wait<0>();
        }
        __syncthreads();

        const float* __restrict__ sa = As[cur];
        const float* __restrict__ sb = Bs[cur];
#pragma unroll
        for (int ks = 0; ks < 4; ks++) {
            int s0 = (ks * 2) ^ gid;
            int s1 = s0 ^ 1;
            uint32_t af[2][4];
#pragma unroll
            for (int mt = 0; mt < 2; mt++) {
                int r = (wm * 32 + mt * 16 + gid) * 32;
                af[mt][0] = __float_as_uint(tf32r(sa[r       + s0 * 4 + tg]));
                af[mt][1] = __float_as_uint(tf32r(sa[r + 256 + s0 * 4 + tg]));
                af[mt][2] = __float_as_uint(tf32r(sa[r       + s1 * 4 + tg]));
                af[mt][3] = __float_as_uint(tf32r(sa[r + 256 + s1 * 4 + tg]));
            }
            uint32_t bf[8][2];
#pragma unroll
            for (int nt = 0; nt < 8; nt++) {
                int rb = (wn * 64 + nt * 8 + gid) * 32;
                bf[nt][0] = __float_as_uint(sb[rb + s0 * 4 + tg]);
                bf[nt][1] = __float_as_uint(sb[rb + s1 * 4 + tg]);
            }
#pragma unroll
            for (int mt = 0; mt < 2; mt++)
#pragma unroll
                for (int nt = 0; nt < 8; nt++)
                    mma_tf32(acc[mt][nt], af[mt][0], af[mt][1], af[mt][2], af[mt][3],
                             bf[nt][0], bf[nt][1]);
        }
        __syncthreads();
    }

    // epilogue
#pragma unroll
    for (int mt = 0; mt < 2; mt++) {
        int r0 = m0 + wm * 32 + mt * 16 + gid;
#pragma unroll
        for (int nt = 0; nt < 8; nt++) {
            int cc = n0 + wn * 64 + nt * 8 + tg * 2;
#pragma unroll
            for (int jj = 0; jj < 2; jj++) {
                int gn = cc + jj;
                if (gn >= N) continue;
                float v0 = acc[mt][nt][jj];
                float v1 = acc[mt][nt][2 + jj];
                if (EPI == 1) {
                    float bv = bias[gn];
                    float a0 = sA0[gn - n0];
                    float d0 = softplusf(v0 + bv);
                    float d1 = softplusf(v1 + bv);
                    C[(size_t)r0 * ldc + gn]       = d0;
                    C[(size_t)(r0 + 8) * ldc + gn] = d1;
                    P[(size_t)r0 * ldc + gn]       = __expf(d0 * a0);
                    P[(size_t)(r0 + 8) * ldc + gn] = __expf(d1 * a0);
                } else if (SPLIT == 1) {
                    atomicAdd(&C[(size_t)r0 * ldc + gn], v0);
                    atomicAdd(&C[(size_t)(r0 + 8) * ldc + gn], v1);
                } else {
                    C[(size_t)r0 * ldc + gn]       = v0;
                    C[(size_t)(r0 + 8) * ldc + gn] = v1;
                }
            }
        }
    }
}
#define GEMM_SMEM 66048

// ---------------- utility kernels --------------------------------------------
__global__ void zero_kernel(float* __restrict__ p, int n)
{
    int i = blockIdx.x * blockDim.x + threadIdx.x;
    if (i < n) p[i] = 0.f;
}
// round a float buffer to tf32 (float4 granularity; n % 4 == 0)
__global__ void round_kernel(const float* __restrict__ s, float* __restrict__ d, int n4)
{
    int i = blockIdx.x * blockDim.x + threadIdx.x;
    if (i >= n4) return;
    float4 v = *(const float4*)&s[i * 4];
    v.x = tf32r(v.x); v.y = tf32r(v.y); v.z = tf32r(v.z); v.w = tf32r(v.w);
    *(float4*)&d[i * 4] = v;
}

// ------ depthwise causal (fwd) + anti-causal (rev) conv + silu, float4 -------
__global__ void conv_silu_kernel(const float* __restrict__ xz,
                                 const float* __restrict__ wf, const float* __restrict__ bf,
                                 const float* __restrict__ wr, const float* __restrict__ br,
                                 float* __restrict__ uf, float* __restrict__ ur)
{
    int v = blockIdx.x * blockDim.x + threadIdx.x;
    const int ND4 = DINNER / 4;
    if (v >= MTOK * ND4) return;
    int d4 = v % ND4;
    int t  = (v / ND4) % LL;
    int b  = v / (ND4 * LL);
    int d  = d4 * 4;

    const float* base = xz + (size_t)b * LL * XZW + d;

    float4 Wf[4], Wr[4];
#pragma unroll
    for (int j = 0; j < 4; j++) {
        Wf[j] = *(const float4*)&wf[(d + j) * DCONV];
        Wr[j] = *(const float4*)&wr[(d + j) * DCONV];
    }
    float4 accf = *(const float4*)&bf[d];
    float4 accr = *(const float4*)&br[d];

#pragma unroll
    for (int k = 0; k < DCONV; k++) {
        int tf = t - (DCONV - 1) + k;
        int tr = t + (DCONV - 1) - k;
        float4 vf = (tf >= 0) ? *(const float4*)(base + (size_t)tf * XZW)
                              : make_float4(0.f, 0.f, 0.f, 0.f);
        float4 vr = (tr < LL) ? *(const float4*)(base + (size_t)tr * XZW)
                              : make_float4(0.f, 0.f, 0.f, 0.f);
        const float wfk[4] = { ((const float*)&Wf[0])[k], ((const float*)&Wf[1])[k],
                               ((const float*)&Wf[2])[k], ((const float*)&Wf[3])[k] };
        const float wrk[4] = { ((const float*)&Wr[0])[k], ((const float*)&Wr[1])[k],
                               ((const float*)&Wr[2])[k], ((const float*)&Wr[3])[k] };
        accf.x = fmaf(wfk[0], vf.x, accf.x);
        accf.y = fmaf(wfk[1], vf.y, accf.y);
        accf.z = fmaf(wfk[2], vf.z, accf.z);
        accf.w = fmaf(wfk[3], vf.w, accf.w);
        accr.x = fmaf(wrk[0], vr.x, accr.x);
        accr.y = fmaf(wrk[1], vr.y, accr.y);
        accr.z = fmaf(wrk[2], vr.z, accr.z);
        accr.w = fmaf(wrk[3], vr.w, accr.w);
    }
    size_t o = (size_t)(b * LL + t) * DINNER + d;
    *(float4*)&uf[o] = make_float4(siluf(accf.x), siluf(accf.y), siluf(accf.z), siluf(accf.w));
    *(float4*)&ur[o] = make_float4(siluf(accr.x), siluf(accr.y), siluf(accr.z), siluf(accr.w));
}

// ---------------- selective scan, smem-staged (unchanged from R7) -------------
#define SCH  32
#define SCHN 32
__global__ __launch_bounds__(128)
void scan_kernel(const float* __restrict__ de0p, const float* __restrict__ de1p,
                 const float* __restrict__ gp0,  const float* __restrict__ gp1,
                 const float* __restrict__ xd0p, const float* __restrict__ xd1p,
                 const float* __restrict__ u0p,  const float* __restrict__ u1p,
                 const float* __restrict__ alf,  const float* __restrict__ alr,
                 const float* __restrict__ Dfp,  const float* __restrict__ Drp,
                 float* __restrict__ y0p, float* __restrict__ y1p)
{
    const int reverse = blockIdx.z;
    const float* __restrict__ delta = reverse ? de1p : de0p;
    const float* __restrict__ gp    = reverse ? gp1  : gp0;
    const float* __restrict__ xdbl  = reverse ? xd1p : xd0p;
    const float* __restrict__ u     = reverse ? u1p  : u0p;
    const float* __restrict__ A_log = reverse ? alr  : alf;
    const float* __restrict__ Dp    = reverse ? Drp  : Dfp;
    float* __restrict__ y           = reverse ? y1p  : y0p;

    __shared__ float sBC[SCH][32];
    __shared__ float sP [SCH][SCHN];
    __shared__ float sDL[SCH][SCHN];
    __shared__ float sU [SCH][SCHN];
    __shared__ float sY [SCH][SCHN];

    const int tid = threadIdx.x;
    const int ch = tid >> 2, tq = tid & 3;
    const int lane = tid & 31;
    const int d0 = blockIdx.x * SCHN;
    const int d = d0 + ch;
    const int b = blockIdx.y;

    float A[4];
#pragma unroll
    for (int j = 0; j < 4; j++)
        A[j] = -__expf(A_log[(size_t)d * DSTATE + tq * 4 + j]);
    float A0 = -__expf(A_log[(size_t)d * DSTATE]);
    bool okl = true;
#pragma unroll
    for (int j = 0; j < 4; j++) {
        float t = (float)(tq * 4 + j + 1) * A0;
        okl = okl && (fabsf(A[j] - t) <= 1e-3f * fabsf(A[j]) + 1e-6f);
    }
    unsigned bal = __ballot_sync(0xffffffffu, okl);
    int qsh = lane & 28;
    bool ok = ((bal >> qsh) & 0xFu) == 0xFu;
    float Dv = Dp[d];

    float h[4] = {0.f, 0.f, 0.f, 0.f};

    for (int c = 0; c < LL / SCH; c++) {
        __syncthreads();
#pragma unroll
        for (int k = 0; k < 2; k++) {
            int fi = tid + k * 128;
            int i  = fi >> 3;
            int qq = fi & 7;
            int tt = reverse ? (LL - 1 - (c * SCH + i)) : (c * SCH + i);
            size_t rb = (size_t)(b * LL + tt) * DINNER + d0 + qq * 4;
            *(float4*)&sP [i][qq * 4] = *(const float4*)&gp[rb];
            *(float4*)&sDL[i][qq * 4] = *(const float4*)&delta[rb];
            *(float4*)&sU [i][qq * 4] = *(const float4*)&u[rb];
            *(float4*)&sBC[i][qq * 4] =
                *(const float4*)&xdbl[(size_t)(b * LL + tt) * XDBLW + DTRANK + qq * 4];
        }
        __syncthreads();

        float pp = sP[0][ch], dl = sDL[0][ch], uu = sU[0][ch];
        float4 Bv = *(const float4*)&sBC[0][tq * 4];
        float4 Cv = *(const float4*)&sBC[0][16 + tq * 4];

        for (int i = 0; i < SCH; i++) {
            float ppn = 0.f, dln = 0.f, uun = 0.f;
            float4 Bn = Bv, Cn = Cv;
            if (i + 1 < SCH) {
                ppn = sP[i + 1][ch]; dln = sDL[i + 1][ch]; uun = sU[i + 1][ch];
                Bn = *(const float4*)&sBC[i + 1][tq * 4];
                Cn = *(const float4*)&sBC[i + 1][16 + tq * 4];
            }
            float du = dl * uu;
            float acc;
            if (ok) {
                float p2 = pp * pp;
                float p3 = p2 * pp;
                float p4 = p2 * p2;
                float p8 = p4 * p4;
                float p12 = p8 * p4;
                float q4 = (tq == 0) ? 1.f : (tq == 1) ? p4 : (tq == 2) ? p8 : p12;
                h[0] = fmaf(q4 * pp, h[0], du * Bv.x);
                h[1] = fmaf(q4 * p2, h[1], du * Bv.y);
                h[2] = fmaf(q4 * p3, h[2], du * Bv.z);
                h[3] = fmaf(q4 * p4, h[3], du * Bv.w);
            } else {
                h[0] = fmaf(__expf(dl * A[0]), h[0], du * Bv.x);
                h[1] = fmaf(__expf(dl * A[1]), h[1], du * Bv.y);
                h[2] = fmaf(__expf(dl * A[2]), h[2], du * Bv.z);
                h[3] = fmaf(__expf(dl * A[3]), h[3], du * Bv.w);
            }
            acc = h[0] * Cv.x;
            acc = fmaf(h[1], Cv.y, acc);
            acc = fmaf(h[2], Cv.z, acc);
            acc = fmaf(h[3], Cv.w, acc);
            acc += __shfl_xor_sync(0xffffffffu, acc, 1);
            acc += __shfl_xor_sync(0xffffffffu, acc, 2);
            if (tq == 0) sY[i][ch] = acc + uu * Dv;
            pp = ppn; dl = dln; uu = uun; Bv = Bn; Cv = Cn;
        }
        __syncthreads();
#pragma unroll
        for (int k = 0; k < 2; k++) {
            int fi = tid + k * 128;
            int i  = fi >> 3;
            int qq = fi & 7;
            int tt = reverse ? (LL - 1 - (c * SCH + i)) : (c * SCH + i);
            *(float4*)&y[(size_t)(b * LL + tt) * DINNER + d0 + qq * 4] =
                *(const float4*)&sY[i][qq * 4];
        }
    }
}

// ---------------- gate + sum both directions, float4 --------------------------
__global__ void combine_kernel(const float* __restrict__ xz,
                               const float* __restrict__ ya,
                               const float* __restrict__ yb,
                               float* __restrict__ yt)
{
    int v = blockIdx.x * blockDim.x + threadIdx.x;
    const int ND4 = DINNER / 4;
    if (v >= MTOK * ND4) return;
    int d4 = v % ND4;
    int m  = v / ND4;
    float4 z  = *(const float4*)&xz[(size_t)m * XZW + DINNER + d4 * 4];
    float4 a  = *(const float4*)&ya[(size_t)m * DINNER + d4 * 4];
    float4 bb = *(const float4*)&yb[(size_t)m * DINNER + d4 * 4];
    float4 o;
    o.x = siluf(z.x) * (a.x + bb.x);
    o.y = siluf(z.y) * (a.y + bb.y);
    o.z = siluf(z.z) * (a.z + bb.z);
    o.w = siluf(z.w) * (a.w + bb.w);
    *(float4*)&yt[(size_t)m * DINNER + d4 * 4] = o;
}

// ---------------- launch -----------------------------------------------------
extern "C" void kernel_launch(void* const* d_in, const int* in_sizes, int n_in,
                              void* d_out, int out_size)
{
    const float* x       = (const float*)d_in[0];
    const float* in_w    = (const float*)d_in[1];
    const float* out_w   = (const float*)d_in[2];
    const float* conv_wf = (const float*)d_in[3];
    const float* conv_bf = (const float*)d_in[4];
    const float* xproj_f = (const float*)d_in[5];
    const float* dt_wf   = (const float*)d_in[6];
    const float* dt_bf   = (const float*)d_in[7];
    const float* alog_f  = (const float*)d_in[8];
    const float* D_f     = (const float*)d_in[9];
    const float* conv_wr = (const float*)d_in[10];
    const float* conv_br = (const float*)d_in[11];
    const float* xproj_r = (const float*)d_in[12];
    const float* dt_wr   = (const float*)d_in[13];
    const float* dt_br   = (const float*)d_in[14];
    const float* alog_r  = (const float*)d_in[15];
    const float* D_r     = (const float*)d_in[16];

    float *xz, *u0, *u1, *xd0, *xd1, *de0, *de1, *p0, *p1, *y0, *y1, *yt;
    float *win, *wout, *wx0, *wx1, *wd0, *wd1;
    cudaGetSymbolAddress((void**)&xz,  g_xz);
    cudaGetSymbolAddress((void**)&u0,  g_u0);
    cudaGetSymbolAddress((void**)&u1,  g_u1);
    cudaGetSymbolAddress((void**)&xd0, g_xd0);
    cudaGetSymbolAddress((void**)&xd1, g_xd1);
    cudaGetSymbolAddress((void**)&de0, g_de0);
    cudaGetSymbolAddress((void**)&de1, g_de1);
    cudaGetSymbolAddress((void**)&p0,  g_p0);
    cudaGetSymbolAddress((void**)&p1,  g_p1);
    cudaGetSymbolAddress((void**)&y0,  g_y0);
    cudaGetSymbolAddress((void**)&y1,  g_y1);
    cudaGetSymbolAddress((void**)&yt,  g_yt);
    cudaGetSymbolAddress((void**)&win,  g_win);
    cudaGetSymbolAddress((void**)&wout, g_wout);
    cudaGetSymbolAddress((void**)&wx0,  g_wx0);
    cudaGetSymbolAddress((void**)&wx1,  g_wx1);
    cudaGetSymbolAddress((void**)&wd0,  g_wd0);
    cudaGetSymbolAddress((void**)&wd1,  g_wd1);

    float* out = (float*)d_out;

    cudaFuncSetAttribute(gemm_tc<0, 0>, cudaFuncAttributeMaxDynamicSharedMemorySize, GEMM_SMEM);
    cudaFuncSetAttribute(gemm_tc<0, 1>, cudaFuncAttributeMaxDynamicSharedMemorySize, GEMM_SMEM);
    cudaFuncSetAttribute(gemm_tc<1, 0>, cudaFuncAttributeMaxDynamicSharedMemorySize, GEMM_SMEM);

    // 0) pre-round weights to tf32 + zero split-K outputs
    {
        int n;
        n = XZW * DMODEL / 4;    round_kernel<<<(n + 255) / 256, 256>>>(in_w,    win,  n);
        n = DMODEL * DINNER / 4; round_kernel<<<(n + 255) / 256, 256>>>(out_w,   wout, n);
        n = XDBLW * DINNER / 4;  round_kernel<<<(n + 255) / 256, 256>>>(xproj_f, wx0,  n);
        n = XDBLW * DINNER / 4;  round_kernel<<<(n + 255) / 256, 256>>>(xproj_r, wx1,  n);
        n = DINNER * DTRANK / 4; round_kernel<<<(n + 255) / 256, 256>>>(dt_wf,   wd0,  n);
        n = DINNER * DTRANK / 4; round_kernel<<<(n + 255) / 256, 256>>>(dt_wr,   wd1,  n);
        zero_kernel<<<(MTOK * XDBLW + 255) / 256, 256>>>(xd0, MTOK * XDBLW);
        zero_kernel<<<(MTOK * XDBLW + 255) / 256, 256>>>(xd1, MTOK * XDBLW);
        zero_kernel<<<(MTOK * DMODEL + 255) / 256, 256>>>(out, MTOK * DMODEL);
    }

    // 1) xz = x @ in_proj_w^T   (2048 x 3072, K=768), shared by both dirs
    {
        dim3 grid(XZW / 128, MTOK / 128, 1);
        gemm_tc<0, 0><<<grid, 256, GEMM_SMEM>>>(x, x, win, win, xz, xz,
                                     nullptr, nullptr, nullptr, nullptr,
                                     nullptr, nullptr,
                                     MTOK, XZW, DMODEL, DMODEL, DMODEL, XZW, 1);
    }
    // 2) depthwise conv + silu, both directions, float4
    {
        int n = MTOK * (DINNER / 4);
        conv_silu_kernel<<<(n + 255) / 256, 256>>>(xz, conv_wf, conv_bf,
                                                   conv_wr, conv_br, u0, u1);
    }
    // 3) x_dbl = u @ x_proj_w^T  (2048 x 80, K=1536), both dirs, split-K=4
    {
        dim3 grid(1, MTOK / 128, 2 * 4);
        gemm_tc<0, 1><<<grid, 256, GEMM_SMEM>>>(u0, u1, wx0, wx1, xd0, xd1,
                                     nullptr, nullptr, nullptr, nullptr,
                                     nullptr, nullptr,
                                     MTOK, XDBLW, DINNER / 4, DINNER, DINNER, XDBLW, 4);
    }
    // 4) delta = softplus(dt @ dt_w^T + dt_b), + p = exp(delta*A0), batched dirs
    {
        dim3 grid(DINNER / 128, MTOK / 128, 2);
        gemm_tc<1, 0><<<grid, 256, GEMM_SMEM>>>(xd0, xd1, wd0, wd1, de0, de1,
                                     dt_bf, dt_br, p0, p1,
                                     alog_f, alog_r,
                                     MTOK, DINNER, DTRANK, XDBLW, DTRANK, DINNER, 1);
    }
    // 5) selective scans, smem-staged
    {
        dim3 grid(DINNER / SCHN, BB, 2);
        scan_kernel<<<grid, 128>>>(de0, de1, p0, p1, xd0, xd1, u0, u1,
                                   alog_f, alog_r, D_f, D_r, y0, y1);
    }
    // 6) gate + sum, float4
    {
        int n = MTOK * (DINNER / 4);
        combine_kernel<<<(n + 255) / 256, 256>>>(xz, y0, y1, yt);
    }
    // 7) out = y_tot @ out_proj_w^T  (2048 x 768, K=1536), split-K=2
    {
        dim3 grid(DMODEL / 128, MTOK / 128, 2);
        gemm_tc<0, 1><<<grid, 256, GEMM_SMEM>>>(yt, yt, wout, wout, out, out,
                                     nullptr, nullptr, nullptr, nullptr,
                                     nullptr, nullptr,
                                     MTOK, DMODEL, DINNER / 2, DINNER, DINNER, DMODEL, 2);
    }
}

// round 9
// speedup vs baseline: 4.0901x; 1.1031x over previous
#include <cuda_runtime.h>
#include <cuda_bf16.h>
#include <math.h>
#include <stdint.h>

// Problem constants
#define BB 2
#define LL 1024
#define DMODEL 768
#define DINNER 1536
#define DSTATE 16
#define DCONV 4
#define DTRANK 48
#define MTOK (BB*LL)              // 2048 token rows
#define XZW (2*DINNER)            // 3072
#define XDBLW (DT_RANK_PAD_NOPE + 80) // (placeholder, real below)
#undef XDBLW
#define XDBLW 80

// ---------------- scratch (device globals; no allocation allowed) ------------
__device__ float g_xz[MTOK * XZW];
__device__ float g_u0[MTOK * DINNER];
__device__ float g_u1[MTOK * DINNER];
__device__ float g_xd0[MTOK * XDBLW];
__device__ float g_xd1[MTOK * XDBLW];
__device__ float g_de0[MTOK * DINNER];
__device__ float g_de1[MTOK * DINNER];
__device__ float g_p0[MTOK * DINNER];
__device__ float g_p1[MTOK * DINNER];
__device__ float g_y0[MTOK * DINNER];
__device__ float g_y1[MTOK * DINNER];
__device__ float g_yt[MTOK * DINNER];
// packed (fragment-order, tf32-rounded) weights
// layout: [ntile][kchunk][4096]: within 4096: [ks(4)][nw(16)][lane(32)][r(2)]
__device__ float g_winp [24 * 24 * 4096];   // in_proj:  N=3072, K=768
__device__ float g_woutp[ 6 * 48 * 4096];   // out_proj: N=768,  K=1536
__device__ float g_wxp0 [ 1 * 48 * 4096];   // x_proj f: N=80,   K=1536
__device__ float g_wxp1 [ 1 * 48 * 4096];
__device__ float g_wdp0 [12 *  2 * 4096];   // dt_w f:   N=1536, K=48(pad 64)
__device__ float g_wdp1 [12 *  2 * 4096];

__device__ __forceinline__ float siluf(float x) {
    return x / (1.f + __expf(-x));
}
__device__ __forceinline__ float softplusf(float x) {
    return (x > 20.f) ? x : log1pf(__expf(x));
}
__device__ __forceinline__ float tf32r(float x) {
    uint32_t u;
    asm("cvt.rna.tf32.f32 %0, %1;" : "=r"(u) : "f"(x));
    return __uint_as_float(u);
}
__device__ __forceinline__ void mma_tf32(float c[4],
                                         uint32_t a0, uint32_t a1, uint32_t a2, uint32_t a3,
                                         uint32_t b0, uint32_t b1) {
    asm volatile(
        "mma.sync.aligned.m16n8k8.row.col.f32.tf32.tf32.f32 "
        "{%0,%1,%2,%3}, {%4,%5,%6,%7}, {%8,%9}, {%0,%1,%2,%3};"
        : "+f"(c[0]), "+f"(c[1]), "+f"(c[2]), "+f"(c[3])
        : "r"(a0), "r"(a1), "r"(a2), "r"(a3), "r"(b0), "r"(b1));
}
__device__ __forceinline__ void cp_async16(uint32_t saddr, const void* g, int bytes) {
    asm volatile("cp.async.cg.shared.global [%0], [%1], 16, %2;"
                 :: "r"(saddr), "l"(g), "r"(bytes));
}
__device__ __forceinline__ void cp_commit() {
    asm volatile("cp.async.commit_group;");
}
template<int PEND>
__device__ __forceinline__ void cp_wait() {
    asm volatile("cp.async.wait_group %0;" :: "n"(PEND));
}

// ---------------- fused prep: pack weights to fragment order + zero bufs -----
#define NSEG 9
struct PrepArgs {
    const float* src[NSEG];
    float*       dst[NSEG];
    int          N[NSEG];
    int          K[NSEG];
    int          nkch[NSEG];
    int          end[NSEG];     // cumulative element counts
    int          type[NSEG];    // 0 = pack, 1 = zero
};
__global__ __launch_bounds__(256)
void prep_kernel(PrepArgs a)
{
    int idx = blockIdx.x * 256 + threadIdx.x;
    int seg = 0, start = 0;
#pragma unroll
    for (int i = 0; i < NSEG; i++) {
        if (idx >= a.end[i]) { seg = i + 1; start = a.end[i]; }
    }
    if (seg >= NSEG) return;
    int local = idx - start;
    if (a.type[seg] == 1) {
        a.dst[seg][local] = 0.f;
        return;
    }
    int block = local >> 12;
    int w     = local & 4095;
    int ks    = w >> 10;
    int nw    = (w >> 6) & 15;
    int lane  = (w >> 1) & 31;
    int r     = w & 1;
    int nkch  = a.nkch[seg];
    int ntile = block / nkch;
    int kch   = block % nkch;
    int n = ntile * 128 + nw * 8 + (lane >> 2);
    int k = kch * 32 + ks * 8 + (lane & 3) + r * 4;
    float v = 0.f;
    if (n < a.N[seg] && k < a.K[seg])
        v = tf32r(a.src[seg][(size_t)n * a.K[seg] + k]);
    a.dst[seg][local] = v;
}

// ---------------- tf32 tensor-core NT GEMM ------------------------------------
// C[m,n] = sum_k A[m,k] * Wp(frag-packed)[n,k].  BM=128, BN=128, BK=32.
// A: cp.async coalesced + XOR swizzle, tf32 round at fragment read.
// B: cp.async from fragment-packed global -> vector LDS.64 fragment reads.
// blockIdx.z = dir*ksplit + kchunk.  EPI=1: softplus+bias, P=exp(d*A0).
// SPLIT=1: atomicAdd into pre-zeroed C.
template<int EPI, int SPLIT>
__global__ __launch_bounds__(256)
void gemm_tc(const float* __restrict__ A0p, const float* __restrict__ A1p,
             const float* __restrict__ Wp0, const float* __restrict__ Wp1,
             float* __restrict__ C0p, float* __restrict__ C1p,
             const float* __restrict__ b0p, const float* __restrict__ b1p,
             float* __restrict__ P0p, float* __restrict__ P1p,
             const float* __restrict__ al0, const float* __restrict__ al1,
             int M, int N, int Kc,
             int lda, int ldc, int ksplit, int nkch_tot)
{
    const int dir = blockIdx.z / ksplit;
    const int kch = blockIdx.z % ksplit;
    const float* __restrict__ A    = dir ? A1p : A0p;
    const float* __restrict__ Wp   = dir ? Wp1 : Wp0;
    float* __restrict__ C          = dir ? C1p : C0p;
    const float* __restrict__ bias = dir ? b1p : b0p;
    float* __restrict__ P          = dir ? P1p : P0p;
    const float* __restrict__ alog = dir ? al1 : al0;

    extern __shared__ float smem[];
    float* As[2] = { smem,         smem + 4096 };
    float* Bs[2] = { smem + 8192,  smem + 12288 };
    float* sA0   = smem + 16384;
    uint32_t sbase = (uint32_t)__cvta_generic_to_shared(smem);

    const int tid  = threadIdx.x;
    const int warp = tid >> 5, lane = tid & 31;
    const int wm = warp & 3, wn = warp >> 2;
    const int gid = lane >> 2, tg = lane & 3;
    const int m0 = blockIdx.y * 128, n0 = blockIdx.x * 128;
    const int kbeg = kch * Kc;

    if (EPI == 1 && tid < 128) {
        int cc = n0 + tid;
        sA0[tid] = (cc < N) ? -__expf(alog[(size_t)cc * DSTATE]) : 0.f;
    }

    // A staging descriptors (XOR-swizzled 128x32 tile)
    const float* aptr[4]; uint32_t aoff[4]; int kslot[4];
#pragma unroll
    for (int i = 0; i < 4; i++) {
        int f = tid + i * 256;
        int row = f >> 3, slot = f & 7;
        kslot[i] = slot * 4;
        aoff[i] = (uint32_t)(row * 32 + (slot ^ (row & 7)) * 4) * 4u;
        aptr[i] = A + (size_t)(m0 + row) * lda + kbeg + slot * 4;
    }
    // B staging: contiguous fragment-packed 16KB blocks
    const float* bbase = Wp + ((size_t)blockIdx.x * nkch_tot + (kbeg >> 5)) * 4096;

    const int nk = (Kc + 31) / 32;

    // stage chunk 0
#pragma unroll
    for (int i = 0; i < 4; i++) {
        int f = tid + i * 256;
        bool vk = kslot[i] < Kc;
        cp_async16(sbase + aoff[i],               aptr[i],     vk ? 16 : 0);
        cp_async16(sbase + 32768u + (uint32_t)f * 16u, bbase + f * 4, 16);
    }
    cp_commit();

    float acc[2][8][4];
#pragma unroll
    for (int mt = 0; mt < 2; mt++)
#pragma unroll
        for (int nt = 0; nt < 8; nt++)
#pragma unroll
            for (int r = 0; r < 4; r++) acc[mt][nt][r] = 0.f;

    for (int ch = 0; ch < nk; ch++) {
        int cur = ch & 1;
        if (ch + 1 < nk) {
            int kc = (ch + 1) * 32;
            uint32_t sa = sbase + (uint32_t)((ch + 1) & 1) * 16384u;
            uint32_t sb = sa + 32768u;
            const float* bnext = bbase + (size_t)(ch + 1) * 4096;
#pragma unroll
            for (int i = 0; i < 4; i++) {
                int f = tid + i * 256;
                bool vk = (kc + kslot[i]) < Kc;
                cp_async16(sa + aoff[i], aptr[i] + kc, vk ? 16 : 0);
                cp_async16(sb + (uint32_t)f * 16u, bnext + f * 4, 16);
            }
            cp_commit();
            cp_wait<1>();
        } else {
            cp_wait<0>();
        }
        __syncthreads();

        const float* __restrict__ sa = As[cur];
        const float* __restrict__ sb = Bs[cur];
#pragma unroll
        for (int ks = 0; ks < 4; ks++) {
            int s0 = (ks * 2) ^ gid;
            int s1 = s0 ^ 1;
            uint32_t af[2][4];
#pragma unroll
            for (int mt = 0; mt < 2; mt++) {
                int r = (wm * 32 + mt * 16 + gid) * 32;
                af[mt][0] = __float_as_uint(tf32r(sa[r       + s0 * 4 + tg]));
                af[mt][1] = __float_as_uint(tf32r(sa[r + 256 + s0 * 4 + tg]));
                af[mt][2] = __float_as_uint(tf32r(sa[r       + s1 * 4 + tg]));
                af[mt][3] = __float_as_uint(tf32r(sa[r + 256 + s1 * 4 + tg]));
            }
            float2 bf[8];
#pragma unroll
            for (int nt = 0; nt < 8; nt++)
                bf[nt] = *(const float2*)&sb[((ks * 16 + wn * 8 + nt) * 32 + lane) * 2];
#pragma unroll
            for (int mt = 0; mt < 2; mt++)
#pragma unroll
                for (int nt = 0; nt < 8; nt++)
                    mma_tf32(acc[mt][nt], af[mt][0], af[mt][1], af[mt][2], af[mt][3],
                             __float_as_uint(bf[nt].x), __float_as_uint(bf[nt].y));
        }
        __syncthreads();
    }

    // epilogue
#pragma unroll
    for (int mt = 0; mt < 2; mt++) {
        int r0 = m0 + wm * 32 + mt * 16 + gid;
#pragma unroll
        for (int nt = 0; nt < 8; nt++) {
            int cc = n0 + wn * 64 + nt * 8 + tg * 2;
#pragma unroll
            for (int jj = 0; jj < 2; jj++) {
                int gn = cc + jj;
                if (gn >= N) continue;
                float v0 = acc[mt][nt][jj];
                float v1 = acc[mt][nt][2 + jj];
                if (EPI == 1) {
                    float bv = bias[gn];
                    float a0 = sA0[gn - n0];
                    float d0 = softplusf(v0 + bv);
                    float d1 = softplusf(v1 + bv);
                    C[(size_t)r0 * ldc + gn]       = d0;
                    C[(size_t)(r0 + 8) * ldc + gn] = d1;
                    P[(size_t)r0 * ldc + gn]       = __expf(d0 * a0);
                    P[(size_t)(r0 + 8) * ldc + gn] = __expf(d1 * a0);
                } else if (SPLIT == 1) {
                    atomicAdd(&C[(size_t)r0 * ldc + gn], v0);
                    atomicAdd(&C[(size_t)(r0 + 8) * ldc + gn], v1);
                } else {
                    C[(size_t)r0 * ldc + gn]       = v0;
                    C[(size_t)(r0 + 8) * ldc + gn] = v1;
                }
            }
        }
    }
}
#define GEMM_SMEM 66048

// ------ depthwise causal (fwd) + anti-causal (rev) conv + silu, float4 -------
__global__ void conv_silu_kernel(const float* __restrict__ xz,
                                 const float* __restrict__ wf, const float* __restrict__ bf,
                                 const float* __restrict__ wr, const float* __restrict__ br,
                                 float* __restrict__ uf, float* __restrict__ ur)
{
    int v = blockIdx.x * blockDim.x + threadIdx.x;
    const int ND4 = DINNER / 4;
    if (v >= MTOK * ND4) return;
    int d4 = v % ND4;
    int t  = (v / ND4) % LL;
    int b  = v / (ND4 * LL);
    int d  = d4 * 4;

    const float* base = xz + (size_t)b * LL * XZW + d;

    float4 Wf[4], Wr[4];
#pragma unroll
    for (int j = 0; j < 4; j++) {
        Wf[j] = *(const float4*)&wf[(d + j) * DCONV];
        Wr[j] = *(const float4*)&wr[(d + j) * DCONV];
    }
    float4 accf = *(const float4*)&bf[d];
    float4 accr = *(const float4*)&br[d];

#pragma unroll
    for (int k = 0; k < DCONV; k++) {
        int tf = t - (DCONV - 1) + k;
        int tr = t + (DCONV - 1) - k;
        float4 vf = (tf >= 0) ? *(const float4*)(base + (size_t)tf * XZW)
                              : make_float4(0.f, 0.f, 0.f, 0.f);
        float4 vr = (tr < LL) ? *(const float4*)(base + (size_t)tr * XZW)
                              : make_float4(0.f, 0.f, 0.f, 0.f);
        const float wfk[4] = { ((const float*)&Wf[0])[k], ((const float*)&Wf[1])[k],
                               ((const float*)&Wf[2])[k], ((const float*)&Wf[3])[k] };
        const float wrk[4] = { ((const float*)&Wr[0])[k], ((const float*)&Wr[1])[k],
                               ((const float*)&Wr[2])[k], ((const float*)&Wr[3])[k] };
        accf.x = fmaf(wfk[0], vf.x, accf.x);
        accf.y = fmaf(wfk[1], vf.y, accf.y);
        accf.z = fmaf(wfk[2], vf.z, accf.z);
        accf.w = fmaf(wfk[3], vf.w, accf.w);
        accr.x = fmaf(wrk[0], vr.x, accr.x);
        accr.y = fmaf(wrk[1], vr.y, accr.y);
        accr.z = fmaf(wrk[2], vr.z, accr.z);
        accr.w = fmaf(wrk[3], vr.w, accr.w);
    }
    size_t o = (size_t)(b * LL + t) * DINNER + d;
    *(float4*)&uf[o] = make_float4(siluf(accf.x), siluf(accf.y), siluf(accf.z), siluf(accf.w));
    *(float4*)&ur[o] = make_float4(siluf(accr.x), siluf(accr.y), siluf(accr.z), siluf(accr.w));
}

// ---------------- selective scan, smem-staged ---------------------------------
#define SCH  32
#define SCHN 32
__global__ __launch_bounds__(128)
void scan_kernel(const float* __restrict__ de0p, const float* __restrict__ de1p,
                 const float* __restrict__ gp0,  const float* __restrict__ gp1,
                 const float* __restrict__ xd0p, const float* __restrict__ xd1p,
                 const float* __restrict__ u0p,  const float* __restrict__ u1p,
                 const float* __restrict__ alf,  const float* __restrict__ alr,
                 const float* __restrict__ Dfp,  const float* __restrict__ Drp,
                 float* __restrict__ y0p, float* __restrict__ y1p)
{
    const int reverse = blockIdx.z;
    const float* __restrict__ delta = reverse ? de1p : de0p;
    const float* __restrict__ gp    = reverse ? gp1  : gp0;
    const float* __restrict__ xdbl  = reverse ? xd1p : xd0p;
    const float* __restrict__ u     = reverse ? u1p  : u0p;
    const float* __restrict__ A_log = reverse ? alr  : alf;
    const float* __restrict__ Dp    = reverse ? Drp  : Dfp;
    float* __restrict__ y           = reverse ? y1p  : y0p;

    __shared__ float sBC[SCH][32];
    __shared__ float sP [SCH][SCHN];
    __shared__ float sDL[SCH][SCHN];
    __shared__ float sU [SCH][SCHN];
    __shared__ float sY [SCH][SCHN];

    const int tid = threadIdx.x;
    const int ch = tid >> 2, tq = tid & 3;
    const int lane = tid & 31;
    const int d0 = blockIdx.x * SCHN;
    const int d = d0 + ch;
    const int b = blockIdx.y;

    float A[4];
#pragma unroll
    for (int j = 0; j < 4; j++)
        A[j] = -__expf(A_log[(size_t)d * DSTATE + tq * 4 + j]);
    float A0 = -__expf(A_log[(size_t)d * DSTATE]);
    bool okl = true;
#pragma unroll
    for (int j = 0; j < 4; j++) {
        float t = (float)(tq * 4 + j + 1) * A0;
        okl = okl && (fabsf(A[j] - t) <= 1e-3f * fabsf(A[j]) + 1e-6f);
    }
    unsigned bal = __ballot_sync(0xffffffffu, okl);
    int qsh = lane & 28;
    bool ok = ((bal >> qsh) & 0xFu) == 0xFu;
    float Dv = Dp[d];

    float h[4] = {0.f, 0.f, 0.f, 0.f};

    for (int c = 0; c < LL / SCH; c++) {
        __syncthreads();
#pragma unroll
        for (int k = 0; k < 2; k++) {
            int fi = tid + k * 128;
            int i  = fi >> 3;
            int qq = fi & 7;
            int tt = reverse ? (LL - 1 - (c * SCH + i)) : (c * SCH + i);
            size_t rb = (size_t)(b * LL + tt) * DINNER + d0 + qq * 4;
            *(float4*)&sP [i][qq * 4] = *(const float4*)&gp[rb];
            *(float4*)&sDL[i][qq * 4] = *(const float4*)&delta[rb];
            *(float4*)&sU [i][qq * 4] = *(const float4*)&u[rb];
            *(float4*)&sBC[i][qq * 4] =
                *(const float4*)&xdbl[(size_t)(b * LL + tt) * XDBLW + DTRANK + qq * 4];
        }
        __syncthreads();

        float pp = sP[0][ch], dl = sDL[0][ch], uu = sU[0][ch];
        float4 Bv = *(const float4*)&sBC[0][tq * 4];
        float4 Cv = *(const float4*)&sBC[0][16 + tq * 4];

        for (int i = 0; i < SCH; i++) {
            float ppn = 0.f, dln = 0.f, uun = 0.f;
            float4 Bn = Bv, Cn = Cv;
            if (i + 1 < SCH) {
                ppn = sP[i + 1][ch]; dln = sDL[i + 1][ch]; uun = sU[i + 1][ch];
                Bn = *(const float4*)&sBC[i + 1][tq * 4];
                Cn = *(const float4*)&sBC[i + 1][16 + tq * 4];
            }
            float du = dl * uu;
            float acc;
            if (ok) {
                float p2 = pp * pp;
                float p3 = p2 * pp;
                float p4 = p2 * p2;
                float p8 = p4 * p4;
                float p12 = p8 * p4;
                float q4 = (tq == 0) ? 1.f : (tq == 1) ? p4 : (tq == 2) ? p8 : p12;
                h[0] = fmaf(q4 * pp, h[0], du * Bv.x);
                h[1] = fmaf(q4 * p2, h[1], du * Bv.y);
                h[2] = fmaf(q4 * p3, h[2], du * Bv.z);
                h[3] = fmaf(q4 * p4, h[3], du * Bv.w);
            } else {
                h[0] = fmaf(__expf(dl * A[0]), h[0], du * Bv.x);
                h[1] = fmaf(__expf(dl * A[1]), h[1], du * Bv.y);
                h[2] = fmaf(__expf(dl * A[2]), h[2], du * Bv.z);
                h[3] = fmaf(__expf(dl * A[3]), h[3], du * Bv.w);
            }
            acc = h[0] * Cv.x;
            acc = fmaf(h[1], Cv.y, acc);
            acc = fmaf(h[2], Cv.z, acc);
            acc = fmaf(h[3], Cv.w, acc);
            acc += __shfl_xor_sync(0xffffffffu, acc, 1);
            acc += __shfl_xor_sync(0xffffffffu, acc, 2);
            if (tq == 0) sY[i][ch] = acc + uu * Dv;
            pp = ppn; dl = dln; uu = uun; Bv = Bn; Cv = Cn;
        }
        __syncthreads();
#pragma unroll
        for (int k = 0; k < 2; k++) {
            int fi = tid + k * 128;
            int i  = fi >> 3;
            int qq = fi & 7;
            int tt = reverse ? (LL - 1 - (c * SCH + i)) : (c * SCH + i);
            *(float4*)&y[(size_t)(b * LL + tt) * DINNER + d0 + qq * 4] =
                *(const float4*)&sY[i][qq * 4];
        }
    }
}

// ---------------- gate + sum both directions, float4 --------------------------
__global__ void combine_kernel(const float* __restrict__ xz,
                               const float* __restrict__ ya,
                               const float* __restrict__ yb,
                               float* __restrict__ yt)
{
    int v = blockIdx.x * blockDim.x + threadIdx.x;
    const int ND4 = DINNER / 4;
    if (v >= MTOK * ND4) return;
    int d4 = v % ND4;
    int m  = v / ND4;
    float4 z  = *(const float4*)&xz[(size_t)m * XZW + DINNER + d4 * 4];
    float4 a  = *(const float4*)&ya[(size_t)m * DINNER + d4 * 4];
    float4 bb = *(const float4*)&yb[(size_t)m * DINNER + d4 * 4];
    float4 o;
    o.x = siluf(z.x) * (a.x + bb.x);
    o.y = siluf(z.y) * (a.y + bb.y);
    o.z = siluf(z.z) * (a.z + bb.z);
    o.w = siluf(z.w) * (a.w + bb.w);
    *(float4*)&yt[(size_t)m * DINNER + d4 * 4] = o;
}

// ---------------- launch -----------------------------------------------------
extern "C" void kernel_launch(void* const* d_in, const int* in_sizes, int n_in,
                              void* d_out, int out_size)
{
    const float* x       = (const float*)d_in[0];
    const float* in_w    = (const float*)d_in[1];
    const float* out_w   = (const float*)d_in[2];
    const float* conv_wf = (const float*)d_in[3];
    const float* conv_bf = (const float*)d_in[4];
    const float* xproj_f = (const float*)d_in[5];
    const float* dt_wf   = (const float*)d_in[6];
    const float* dt_bf   = (const float*)d_in[7];
    const float* alog_f  = (const float*)d_in[8];
    const float* D_f     = (const float*)d_in[9];
    const float* conv_wr = (const float*)d_in[10];
    const float* conv_br = (const float*)d_in[11];
    const float* xproj_r = (const float*)d_in[12];
    const float* dt_wr   = (const float*)d_in[13];
    const float* dt_br   = (const float*)d_in[14];
    const float* alog_r  = (const float*)d_in[15];
    const float* D_r     = (const float*)d_in[16];

    float *xz, *u0, *u1, *xd0, *xd1, *de0, *de1, *p0, *p1, *y0, *y1, *yt;
    float *winp, *woutp, *wxp0, *wxp1, *wdp0, *wdp1;
    cudaGetSymbolAddress((void**)&xz,  g_xz);
    cudaGetSymbolAddress((void**)&u0,  g_u0);
    cudaGetSymbolAddress((void**)&u1,  g_u1);
    cudaGetSymbolAddress((void**)&xd0, g_xd0);
    cudaGetSymbolAddress((void**)&xd1, g_xd1);
    cudaGetSymbolAddress((void**)&de0, g_de0);
    cudaGetSymbolAddress((void**)&de1, g_de1);
    cudaGetSymbolAddress((void**)&p0,  g_p0);
    cudaGetSymbolAddress((void**)&p1,  g_p1);
    cudaGetSymbolAddress((void**)&y0,  g_y0);
    cudaGetSymbolAddress((void**)&y1,  g_y1);
    cudaGetSymbolAddress((void**)&yt,  g_yt);
    cudaGetSymbolAddress((void**)&winp,  g_winp);
    cudaGetSymbolAddress((void**)&woutp, g_woutp);
    cudaGetSymbolAddress((void**)&wxp0,  g_wxp0);
    cudaGetSymbolAddress((void**)&wxp1,  g_wxp1);
    cudaGetSymbolAddress((void**)&wdp0,  g_wdp0);
    cudaGetSymbolAddress((void**)&wdp1,  g_wdp1);

    float* out = (float*)d_out;

    cudaFuncSetAttribute(gemm_tc<0, 0>, cudaFuncAttributeMaxDynamicSharedMemorySize, GEMM_SMEM);
    cudaFuncSetAttribute(gemm_tc<0, 1>, cudaFuncAttributeMaxDynamicSharedMemorySize, GEMM_SMEM);
    cudaFuncSetAttribute(gemm_tc<1, 0>, cudaFuncAttributeMaxDynamicSharedMemorySize, GEMM_SMEM);

    // 0) fused prep: pack 6 weights (tf32, fragment order) + zero 3 buffers
    {
        PrepArgs a;
        const int c_win  = 24 * 24 * 4096;
        const int c_wout =  6 * 48 * 4096;
        const int c_wx   =  1 * 48 * 4096;
        const int c_wd   = 12 *  2 * 4096;
        const int c_xd   = MTOK * XDBLW;
        const int c_out  = MTOK * DMODEL;
        int e = 0;
        a.src[0]=in_w;    a.dst[0]=winp;  a.N[0]=XZW;    a.K[0]=DMODEL; a.nkch[0]=24; a.type[0]=0; e+=c_win;  a.end[0]=e;
        a.src[1]=out_w;   a.dst[1]=woutp; a.N[1]=DMODEL; a.K[1]=DINNER; a.nkch[1]=48; a.type[1]=0; e+=c_wout; a.end[1]=e;
        a.src[2]=xproj_f; a.dst[2]=wxp0;  a.N[2]=XDBLW;  a.K[2]=DINNER; a.nkch[2]=48; a.type[2]=0; e+=c_wx;   a.end[2]=e;
        a.src[3]=xproj_r; a.dst[3]=wxp1;  a.N[3]=XDBLW;  a.K[3]=DINNER; a.nkch[3]=48; a.type[3]=0; e+=c_wx;   a.end[3]=e;
        a.src[4]=dt_wf;   a.dst[4]=wdp0;  a.N[4]=DINNER; a.K[4]=DTRANK; a.nkch[4]=2;  a.type[4]=0; e+=c_wd;   a.end[4]=e;
        a.src[5]=dt_wr;   a.dst[5]=wdp1;  a.N[5]=DINNER; a.K[5]=DTRANK; a.nkch[5]=2;  a.type[5]=0; e+=c_wd;   a.end[5]=e;
        a.src[6]=nullptr; a.dst[6]=xd0;   a.N[6]=0; a.K[6]=0; a.nkch[6]=1; a.type[6]=1; e+=c_xd;  a.end[6]=e;
        a.src[7]=nullptr; a.dst[7]=xd1;   a.N[7]=0; a.K[7]=0; a.nkch[7]=1; a.type[7]=1; e+=c_xd;  a.end[7]=e;
        a.src[8]=nullptr; a.dst[8]=out;   a.N[8]=0; a.K[8]=0; a.nkch[8]=1; a.type[8]=1; e+=c_out; a.end[8]=e;
        prep_kernel<<<(e + 255) / 256, 256>>>(a);
    }

    // 1) xz = x @ in_proj_w^T   (2048 x 3072, K=768), shared by both dirs
    {
        dim3 grid(XZW / 128, MTOK / 128, 1);
        gemm_tc<0, 0><<<grid, 256, GEMM_SMEM>>>(x, x, winp, winp, xz, xz,
                                     nullptr, nullptr, nullptr, nullptr,
                                     nullptr, nullptr,
                                     MTOK, XZW, DMODEL, DMODEL, XZW, 1, 24);
    }
    // 2) depthwise conv + silu, both directions, float4
    {
        int n = MTOK * (DINNER / 4);
        conv_silu_kernel<<<(n + 255) / 256, 256>>>(xz, conv_wf, conv_bf,
                                                   conv_wr, conv_br, u0, u1);
    }
    // 3) x_dbl = u @ x_proj_w^T  (2048 x 80, K=1536), both dirs, split-K=4
    {
        dim3 grid(1, MTOK / 128, 2 * 4);
        gemm_tc<0, 1><<<grid, 256, GEMM_SMEM>>>(u0, u1, wxp0, wxp1, xd0, xd1,
                                     nullptr, nullptr, nullptr, nullptr,
                                     nullptr, nullptr,
                                     MTOK, XDBLW, DINNER / 4, DINNER, XDBLW, 4, 48);
    }
    // 4) delta = softplus(dt @ dt_w^T + dt_b), + p = exp(delta*A0), batched dirs
    {
        dim3 grid(DINNER / 128, MTOK / 128, 2);
        gemm_tc<1, 0><<<grid, 256, GEMM_SMEM>>>(xd0, xd1, wdp0, wdp1, de0, de1,
                                     dt_bf, dt_br, p0, p1,
                                     alog_f, alog_r,
                                     MTOK, DINNER, DTRANK, XDBLW, DINNER, 1, 2);
    }
    // 5) selective scans, smem-staged
    {
        dim3 grid(DINNER / SCHN, BB, 2);
        scan_kernel<<<grid, 128>>>(de0, de1, p0, p1, xd0, xd1, u0, u1,
                                   alog_f, alog_r, D_f, D_r, y0, y1);
    }
    // 6) gate + sum, float4
    {
        int n = MTOK * (DINNER / 4);
        combine_kernel<<<(n + 255) / 256, 256>>>(xz, y0, y1, yt);
    }
    // 7) out = y_tot @ out_proj_w^T  (2048 x 768, K=1536), split-K=2
    {
        dim3 grid(DMODEL / 128, MTOK / 128, 2);
        gemm_tc<0, 1><<<grid, 256, GEMM_SMEM>>>(yt, yt, woutp, woutp, out, out,
                                     nullptr, nullptr, nullptr, nullptr,
                                     nullptr, nullptr,
                                     MTOK, DMODEL, DINNER / 2, DINNER, DMODEL, 2, 48);
    }
}